// round 2
// baseline (speedup 1.0000x reference)
#include <cuda_runtime.h>
#include <cstdint>
#include <cstddef>

#define N_NODES 50000
#define NUM_REL 8
#define IN_DIM  128
#define HID     256
#define E_EDGES 1600000
#define M_DEC   200000

// ---------------------------------------------------------------------------
// Device scratch (static globals — no allocation allowed)
// ---------------------------------------------------------------------------
__device__ float g_agg[(size_t)N_NODES * NUM_REL * HID];          // 409.6 MB (layer1 uses first N*8*128)
__device__ float g_cnt[N_NODES * NUM_REL];
__device__ float g_A[(size_t)N_NODES * (HID + NUM_REL * HID)];    // N x 2304 (layer1 uses N x 1152)
__device__ float g_B[(HID + NUM_REL * HID) * HID];                // 2304 x 256
__device__ float g_hp[(size_t)N_NODES * HID];
__device__ float g_h1[(size_t)N_NODES * HID];
__device__ float g_h [(size_t)N_NODES * HID];
__device__ float g_Z [(size_t)M_DEC * 2 * HID];                   // 409.6 MB
__device__ float g_Z1[(size_t)M_DEC * HID];
__device__ float g_Z2[(size_t)M_DEC * (HID / 2)];

// ---------------------------------------------------------------------------
// Utility: zero a float buffer (n must be divisible by 4)
// ---------------------------------------------------------------------------
__global__ void zero_kernel(float* __restrict__ p, long long n4) {
    long long i = (long long)blockIdx.x * blockDim.x + threadIdx.x;
    if (i < n4) ((float4*)p)[i] = make_float4(0.f, 0.f, 0.f, 0.f);
}

// ---------------------------------------------------------------------------
// Edge aggregation: scatter-add feat[src] into g_agg[dst, rel, :], count edges
// One warp (DIM=128) or two warps (DIM=256) per edge; float4 lanes.
// ---------------------------------------------------------------------------
template <int DIM>
__global__ void aggregate_kernel(const float* __restrict__ feat,
                                 const int* __restrict__ ei,
                                 const int* __restrict__ et) {
    const int L = DIM / 4;
    long long t = (long long)blockIdx.x * blockDim.x + threadIdx.x;
    int e    = (int)(t / L);
    int lane = (int)(t % L);
    if (e >= E_EDGES) return;
    int src = ei[e];
    int dst = ei[E_EDGES + e];
    int r   = et[e];
    float4 v = *(const float4*)(feat + (size_t)src * DIM + lane * 4);
    float* dp = g_agg + ((size_t)dst * NUM_REL + r) * DIM + lane * 4;
    atomicAdd(dp + 0, v.x);
    atomicAdd(dp + 1, v.y);
    atomicAdd(dp + 2, v.z);
    atomicAdd(dp + 3, v.w);
    if (lane == 0) atomicAdd(&g_cnt[dst * NUM_REL + r], 1.0f);
}

// ---------------------------------------------------------------------------
// Build concatenated A = [feat | agg_0/cnt_0 | ... | agg_7/cnt_7]  (N x 9*DIM)
// ---------------------------------------------------------------------------
template <int DIN>
__global__ void build_A_kernel(const float* __restrict__ feat) {
    const int K = DIN * (NUM_REL + 1);
    long long idx = (long long)blockIdx.x * blockDim.x + threadIdx.x;
    long long total = (long long)N_NODES * K;
    if (idx >= total) return;
    int n = (int)(idx / K);
    int k = (int)(idx % K);
    float v;
    if (k < DIN) {
        v = feat[(size_t)n * DIN + k];
    } else {
        int r = (k - DIN) / DIN;
        int j = (k - DIN) % DIN;
        float c = g_cnt[n * NUM_REL + r];
        v = g_agg[((size_t)n * NUM_REL + r) * DIN + j] / fmaxf(c, 1.0f);
    }
    g_A[idx] = v;
}

// ---------------------------------------------------------------------------
// Build concatenated B = [root; W_0; ...; W_7]  ((9*Kin) x HID)
// ---------------------------------------------------------------------------
__global__ void build_B_kernel(const float* __restrict__ root,
                               const float* __restrict__ W, int Kin) {
    int total = Kin * (NUM_REL + 1) * HID;
    int idx = blockIdx.x * blockDim.x + threadIdx.x;
    if (idx >= total) return;
    int rootN = Kin * HID;
    g_B[idx] = (idx < rootN) ? root[idx] : W[idx - rootN];
}

// ---------------------------------------------------------------------------
// SGEMM: C[M,N] = A[M,K] @ B[K,N] + bias[N], optional exact GELU.
// 128x128 block tile, 8x8 micro-tile, BK=8, 256 threads.
// Requires: K % 8 == 0, N % 128 == 0 (true for all uses: K in {1152,2304,512,256},
// N in {256,128}). M guarded.
// ---------------------------------------------------------------------------
__global__ __launch_bounds__(256)
void gemm_kernel(const float* __restrict__ A, const float* __restrict__ B,
                 float* __restrict__ C, const float* __restrict__ bias,
                 int M, int N, int K, int act) {
    __shared__ float As[8][128];
    __shared__ float Bs[8][128];
    int tid  = threadIdx.x;
    int brow = blockIdx.y * 128;
    int bcol = blockIdx.x * 128;
    int tr = tid >> 4;            // 0..15
    int tc = tid & 15;            // 0..15

    float acc[8][8];
#pragma unroll
    for (int i = 0; i < 8; i++)
#pragma unroll
        for (int j = 0; j < 8; j++) acc[i][j] = 0.f;

    int arow = tid >> 1;          // 0..127
    int acol = (tid & 1) * 4;     // 0 or 4
    int brw  = tid >> 5;          // 0..7
    int bcl  = (tid & 31) * 4;    // 0..124

    for (int k0 = 0; k0 < K; k0 += 8) {
        float4 av = make_float4(0.f, 0.f, 0.f, 0.f);
        int gr = brow + arow;
        if (gr < M) av = *(const float4*)(A + (size_t)gr * K + k0 + acol);
        As[acol + 0][arow] = av.x;
        As[acol + 1][arow] = av.y;
        As[acol + 2][arow] = av.z;
        As[acol + 3][arow] = av.w;
        float4 bv = *(const float4*)(B + (size_t)(k0 + brw) * N + bcol + bcl);
        *(float4*)&Bs[brw][bcl] = bv;
        __syncthreads();
#pragma unroll
        for (int kk = 0; kk < 8; kk++) {
            float a[8], b[8];
            *(float4*)&a[0] = *(const float4*)&As[kk][tr * 8];
            *(float4*)&a[4] = *(const float4*)&As[kk][tr * 8 + 4];
            *(float4*)&b[0] = *(const float4*)&Bs[kk][tc * 8];
            *(float4*)&b[4] = *(const float4*)&Bs[kk][tc * 8 + 4];
#pragma unroll
            for (int i = 0; i < 8; i++)
#pragma unroll
                for (int j = 0; j < 8; j++)
                    acc[i][j] = fmaf(a[i], b[j], acc[i][j]);
        }
        __syncthreads();
    }

#pragma unroll
    for (int i = 0; i < 8; i++) {
        int row = brow + tr * 8 + i;
        if (row >= M) continue;
#pragma unroll
        for (int j = 0; j < 8; j++) {
            int col = bcol + tc * 8 + j;
            float v = acc[i][j] + bias[col];
            if (act == 1) v = 0.5f * v * (1.0f + erff(v * 0.70710678118654752f));
            C[(size_t)row * N + col] = v;
        }
    }
}

// ---------------------------------------------------------------------------
// Row-wise ReLU + LayerNorm (+ optional residual add): out = resid + LN(relu(hp))
// One 256-thread block per row.
// ---------------------------------------------------------------------------
__global__ void relu_ln_kernel(const float* __restrict__ hp,
                               const float* __restrict__ g,
                               const float* __restrict__ b,
                               float* __restrict__ out,
                               const float* __restrict__ resid) {
    int row = blockIdx.x;
    int tid = threadIdx.x;   // 256 == HID
    float v = fmaxf(hp[(size_t)row * HID + tid], 0.0f);

    __shared__ float red[8];
    __shared__ float s_mu, s_rs;

    float s = v;
#pragma unroll
    for (int o = 16; o; o >>= 1) s += __shfl_xor_sync(0xFFFFFFFFu, s, o);
    if ((tid & 31) == 0) red[tid >> 5] = s;
    __syncthreads();
    if (tid == 0) {
        float t = 0.f;
#pragma unroll
        for (int i = 0; i < 8; i++) t += red[i];
        s_mu = t / (float)HID;
    }
    __syncthreads();

    float d = v - s_mu;
    float s2 = d * d;
#pragma unroll
    for (int o = 16; o; o >>= 1) s2 += __shfl_xor_sync(0xFFFFFFFFu, s2, o);
    if ((tid & 31) == 0) red[tid >> 5] = s2;
    __syncthreads();
    if (tid == 0) {
        float t = 0.f;
#pragma unroll
        for (int i = 0; i < 8; i++) t += red[i];
        s_rs = rsqrtf(t / (float)HID + 1e-5f);
    }
    __syncthreads();

    float o = d * s_rs * g[tid] + b[tid];
    if (resid) o += resid[(size_t)row * HID + tid];
    out[(size_t)row * HID + tid] = o;
}

// ---------------------------------------------------------------------------
// Build decoder input Z[m, 0:256] = h[dec[m,0]], Z[m, 256:512] = h[dec[m,1]]
// ---------------------------------------------------------------------------
__global__ void build_Z_kernel(const int* __restrict__ dec) {
    long long idx = (long long)blockIdx.x * blockDim.x + threadIdx.x;
    long long total = (long long)M_DEC * 512;
    if (idx >= total) return;
    int m = (int)(idx >> 9);
    int k = (int)(idx & 511);
    int node = dec[m * 2 + (k >> 8)];
    g_Z[idx] = g_h[(size_t)node * HID + (k & 255)];
}

// ---------------------------------------------------------------------------
// Final tiny GEMM: out[m, 0:2] = Z2[m,:] @ w3[128,2] + b3.  One warp per row.
// ---------------------------------------------------------------------------
__global__ void final_kernel(const float* __restrict__ w3,
                             const float* __restrict__ b3,
                             float* __restrict__ out) {
    long long t = (long long)blockIdx.x * blockDim.x + threadIdx.x;
    int m = (int)(t >> 5);
    int lane = (int)(t & 31);
    if (m >= M_DEC) return;
    float4 z = *(const float4*)(g_Z2 + (size_t)m * 128 + lane * 4);
    const float* w = w3 + lane * 4 * 2;
    float s0 = z.x * w[0] + z.y * w[2] + z.z * w[4] + z.w * w[6];
    float s1 = z.x * w[1] + z.y * w[3] + z.z * w[5] + z.w * w[7];
#pragma unroll
    for (int o = 16; o; o >>= 1) {
        s0 += __shfl_xor_sync(0xFFFFFFFFu, s0, o);
        s1 += __shfl_xor_sync(0xFFFFFFFFu, s1, o);
    }
    if (lane == 0) {
        out[m * 2 + 0] = s0 + b3[0];
        out[m * 2 + 1] = s1 + b3[1];
    }
}

// ---------------------------------------------------------------------------
// Host launcher
// ---------------------------------------------------------------------------
static inline int blocks_for(long long n, int bs) { return (int)((n + bs - 1) / bs); }

extern "C" void kernel_launch(void* const* d_in, const int* in_sizes, int n_in,
                              void* d_out, int out_size) {
    const float* x     = (const float*)d_in[0];
    const int*   ei    = (const int*)  d_in[1];
    const int*   et    = (const int*)  d_in[2];
    const int*   dec   = (const int*)  d_in[3];
    const float* W1    = (const float*)d_in[4];
    const float* root1 = (const float*)d_in[5];
    const float* b1    = (const float*)d_in[6];
    const float* W2    = (const float*)d_in[7];
    const float* root2 = (const float*)d_in[8];
    const float* b2    = (const float*)d_in[9];
    const float* ln1g  = (const float*)d_in[10];
    const float* ln1b  = (const float*)d_in[11];
    const float* ln2g  = (const float*)d_in[12];
    const float* ln2b  = (const float*)d_in[13];
    const float* mw1   = (const float*)d_in[14];
    const float* mb1   = (const float*)d_in[15];
    const float* mw2   = (const float*)d_in[16];
    const float* mb2   = (const float*)d_in[17];
    const float* mw3   = (const float*)d_in[18];
    const float* mb3   = (const float*)d_in[19];
    float* out = (float*)d_out;

    float *agg, *cnt, *A, *B, *hp, *h1, *h, *Z, *Z1, *Z2;
    cudaGetSymbolAddress((void**)&agg, g_agg);
    cudaGetSymbolAddress((void**)&cnt, g_cnt);
    cudaGetSymbolAddress((void**)&A,   g_A);
    cudaGetSymbolAddress((void**)&B,   g_B);
    cudaGetSymbolAddress((void**)&hp,  g_hp);
    cudaGetSymbolAddress((void**)&h1,  g_h1);
    cudaGetSymbolAddress((void**)&h,   g_h);
    cudaGetSymbolAddress((void**)&Z,   g_Z);
    cudaGetSymbolAddress((void**)&Z1,  g_Z1);
    cudaGetSymbolAddress((void**)&Z2,  g_Z2);

    // ===================== Layer 1 (K = 128 + 8*128 = 1152) =====================
    {
        long long aggN = (long long)N_NODES * NUM_REL * IN_DIM;
        zero_kernel<<<blocks_for(aggN / 4, 256), 256>>>(agg, aggN / 4);
        zero_kernel<<<blocks_for(N_NODES * NUM_REL / 4, 256), 256>>>(cnt, N_NODES * NUM_REL / 4);

        long long aggT = (long long)E_EDGES * (IN_DIM / 4);
        aggregate_kernel<IN_DIM><<<blocks_for(aggT, 256), 256>>>(x, ei, et);

        long long aT = (long long)N_NODES * 1152;
        build_A_kernel<IN_DIM><<<blocks_for(aT, 256), 256>>>(x);
        build_B_kernel<<<blocks_for(1152 * HID, 256), 256>>>(root1, W1, IN_DIM);

        dim3 grid(HID / 128, (N_NODES + 127) / 128);
        gemm_kernel<<<grid, 256>>>(A, B, hp, b1, N_NODES, HID, 1152, 0);

        relu_ln_kernel<<<N_NODES, HID>>>(hp, ln1g, ln1b, h1, nullptr);
    }

    // ===================== Layer 2 (K = 256 + 8*256 = 2304) =====================
    {
        long long aggN = (long long)N_NODES * NUM_REL * HID;
        zero_kernel<<<blocks_for(aggN / 4, 256), 256>>>(agg, aggN / 4);
        zero_kernel<<<blocks_for(N_NODES * NUM_REL / 4, 256), 256>>>(cnt, N_NODES * NUM_REL / 4);

        long long aggT = (long long)E_EDGES * (HID / 4);
        aggregate_kernel<HID><<<blocks_for(aggT, 256), 256>>>(h1, ei, et);

        long long aT = (long long)N_NODES * 2304;
        build_A_kernel<HID><<<blocks_for(aT, 256), 256>>>(h1);
        build_B_kernel<<<blocks_for(2304 * HID, 256), 256>>>(root2, W2, HID);

        dim3 grid(HID / 128, (N_NODES + 127) / 128);
        gemm_kernel<<<grid, 256>>>(A, B, hp, b2, N_NODES, HID, 2304, 0);

        relu_ln_kernel<<<N_NODES, HID>>>(hp, ln2g, ln2b, h, h1);
    }

    // ===================== Decoder =====================
    {
        long long zT = (long long)M_DEC * 512;
        build_Z_kernel<<<blocks_for(zT, 256), 256>>>(dec);

        dim3 g1(HID / 128, (M_DEC + 127) / 128);
        gemm_kernel<<<g1, 256>>>(Z, mw1, Z1, mb1, M_DEC, HID, 2 * HID, 1);

        dim3 g2((HID / 2) / 128, (M_DEC + 127) / 128);
        gemm_kernel<<<g2, 256>>>(Z1, mw2, Z2, mb2, M_DEC, HID / 2, HID, 1);

        final_kernel<<<blocks_for((long long)M_DEC * 32, 256), 256>>>(mw3, mb3, out);
    }
}

// round 3
// speedup vs baseline: 1.0011x; 1.0011x over previous
#include <cuda_runtime.h>
#include <cstdint>
#include <cstddef>

#define N_NODES 50000
#define NUM_REL 8
#define IN_DIM  128
#define HID     256
#define E_EDGES 1600000
#define M_DEC   200000

// ---------------------------------------------------------------------------
// Device scratch (static globals — no allocation allowed)
// ---------------------------------------------------------------------------
__device__ float g_agg[(size_t)N_NODES * NUM_REL * HID];          // 409.6 MB (layer1 uses first N*8*128)
__device__ float g_cnt[N_NODES * NUM_REL];
__device__ float g_A[(size_t)N_NODES * (HID + NUM_REL * HID)];    // N x 2304 (layer1 uses N x 1152)
__device__ float g_B[(HID + NUM_REL * HID) * HID];                // 2304 x 256
__device__ float g_hp[(size_t)N_NODES * HID];
__device__ float g_h1[(size_t)N_NODES * HID];
__device__ float g_h [(size_t)N_NODES * HID];
__device__ float g_Z [(size_t)M_DEC * 2 * HID];                   // 409.6 MB
__device__ float g_Z1[(size_t)M_DEC * HID];
__device__ float g_Z2[(size_t)M_DEC * (HID / 2)];

// ---------------------------------------------------------------------------
// Utility: zero a float buffer (n must be divisible by 4)
// ---------------------------------------------------------------------------
__global__ void zero_kernel(float* __restrict__ p, long long n4) {
    long long i = (long long)blockIdx.x * blockDim.x + threadIdx.x;
    if (i < n4) ((float4*)p)[i] = make_float4(0.f, 0.f, 0.f, 0.f);
}

// ---------------------------------------------------------------------------
// Edge aggregation: scatter-add feat[src] into g_agg[dst, rel, :], count edges
// One warp (DIM=128) or two warps (DIM=256) per edge; float4 lanes.
// ---------------------------------------------------------------------------
template <int DIM>
__global__ void aggregate_kernel(const float* __restrict__ feat,
                                 const int* __restrict__ ei,
                                 const int* __restrict__ et) {
    const int L = DIM / 4;
    long long t = (long long)blockIdx.x * blockDim.x + threadIdx.x;
    int e    = (int)(t / L);
    int lane = (int)(t % L);
    if (e >= E_EDGES) return;
    int src = ei[e];
    int dst = ei[E_EDGES + e];
    int r   = et[e];
    float4 v = *(const float4*)(feat + (size_t)src * DIM + lane * 4);
    float* dp = g_agg + ((size_t)dst * NUM_REL + r) * DIM + lane * 4;
    atomicAdd(dp + 0, v.x);
    atomicAdd(dp + 1, v.y);
    atomicAdd(dp + 2, v.z);
    atomicAdd(dp + 3, v.w);
    if (lane == 0) atomicAdd(&g_cnt[dst * NUM_REL + r], 1.0f);
}

// ---------------------------------------------------------------------------
// Build concatenated A = [feat | agg_0/cnt_0 | ... | agg_7/cnt_7]  (N x 9*DIM)
// ---------------------------------------------------------------------------
template <int DIN>
__global__ void build_A_kernel(const float* __restrict__ feat) {
    const int K = DIN * (NUM_REL + 1);
    long long idx = (long long)blockIdx.x * blockDim.x + threadIdx.x;
    long long total = (long long)N_NODES * K;
    if (idx >= total) return;
    int n = (int)(idx / K);
    int k = (int)(idx % K);
    float v;
    if (k < DIN) {
        v = feat[(size_t)n * DIN + k];
    } else {
        int r = (k - DIN) / DIN;
        int j = (k - DIN) % DIN;
        float c = g_cnt[n * NUM_REL + r];
        v = g_agg[((size_t)n * NUM_REL + r) * DIN + j] / fmaxf(c, 1.0f);
    }
    g_A[idx] = v;
}

// ---------------------------------------------------------------------------
// Build concatenated B = [root; W_0; ...; W_7]  ((9*Kin) x HID)
// ---------------------------------------------------------------------------
__global__ void build_B_kernel(const float* __restrict__ root,
                               const float* __restrict__ W, int Kin) {
    int total = Kin * (NUM_REL + 1) * HID;
    int idx = blockIdx.x * blockDim.x + threadIdx.x;
    if (idx >= total) return;
    int rootN = Kin * HID;
    g_B[idx] = (idx < rootN) ? root[idx] : W[idx - rootN];
}

// ---------------------------------------------------------------------------
// SGEMM: C[M,N] = A[M,K] @ B[K,N] + bias[N], optional exact GELU.
// 128x128 block tile, 8x8 micro-tile, BK=8, 256 threads.
// Requires: K % 8 == 0, N % 128 == 0 (true for all uses: K in {1152,2304,512,256},
// N in {256,128}). M guarded.
// ---------------------------------------------------------------------------
__global__ __launch_bounds__(256)
void gemm_kernel(const float* __restrict__ A, const float* __restrict__ B,
                 float* __restrict__ C, const float* __restrict__ bias,
                 int M, int N, int K, int act) {
    __shared__ float As[8][128];
    __shared__ float Bs[8][128];
    int tid  = threadIdx.x;
    int brow = blockIdx.y * 128;
    int bcol = blockIdx.x * 128;
    int tr = tid >> 4;            // 0..15
    int tc = tid & 15;            // 0..15

    float acc[8][8];
#pragma unroll
    for (int i = 0; i < 8; i++)
#pragma unroll
        for (int j = 0; j < 8; j++) acc[i][j] = 0.f;

    int arow = tid >> 1;          // 0..127
    int acol = (tid & 1) * 4;     // 0 or 4
    int brw  = tid >> 5;          // 0..7
    int bcl  = (tid & 31) * 4;    // 0..124

    for (int k0 = 0; k0 < K; k0 += 8) {
        float4 av = make_float4(0.f, 0.f, 0.f, 0.f);
        int gr = brow + arow;
        if (gr < M) av = *(const float4*)(A + (size_t)gr * K + k0 + acol);
        As[acol + 0][arow] = av.x;
        As[acol + 1][arow] = av.y;
        As[acol + 2][arow] = av.z;
        As[acol + 3][arow] = av.w;
        float4 bv = *(const float4*)(B + (size_t)(k0 + brw) * N + bcol + bcl);
        *(float4*)&Bs[brw][bcl] = bv;
        __syncthreads();
#pragma unroll
        for (int kk = 0; kk < 8; kk++) {
            float a[8], b[8];
            *(float4*)&a[0] = *(const float4*)&As[kk][tr * 8];
            *(float4*)&a[4] = *(const float4*)&As[kk][tr * 8 + 4];
            *(float4*)&b[0] = *(const float4*)&Bs[kk][tc * 8];
            *(float4*)&b[4] = *(const float4*)&Bs[kk][tc * 8 + 4];
#pragma unroll
            for (int i = 0; i < 8; i++)
#pragma unroll
                for (int j = 0; j < 8; j++)
                    acc[i][j] = fmaf(a[i], b[j], acc[i][j]);
        }
        __syncthreads();
    }

#pragma unroll
    for (int i = 0; i < 8; i++) {
        int row = brow + tr * 8 + i;
        if (row >= M) continue;
#pragma unroll
        for (int j = 0; j < 8; j++) {
            int col = bcol + tc * 8 + j;
            float v = acc[i][j] + bias[col];
            if (act == 1) v = 0.5f * v * (1.0f + erff(v * 0.70710678118654752f));
            C[(size_t)row * N + col] = v;
        }
    }
}

// ---------------------------------------------------------------------------
// Row-wise ReLU + LayerNorm (+ optional residual add): out = resid + LN(relu(hp))
// One 256-thread block per row.
// ---------------------------------------------------------------------------
__global__ void relu_ln_kernel(const float* __restrict__ hp,
                               const float* __restrict__ g,
                               const float* __restrict__ b,
                               float* __restrict__ out,
                               const float* __restrict__ resid) {
    int row = blockIdx.x;
    int tid = threadIdx.x;   // 256 == HID
    float v = fmaxf(hp[(size_t)row * HID + tid], 0.0f);

    __shared__ float red[8];
    __shared__ float s_mu, s_rs;

    float s = v;
#pragma unroll
    for (int o = 16; o; o >>= 1) s += __shfl_xor_sync(0xFFFFFFFFu, s, o);
    if ((tid & 31) == 0) red[tid >> 5] = s;
    __syncthreads();
    if (tid == 0) {
        float t = 0.f;
#pragma unroll
        for (int i = 0; i < 8; i++) t += red[i];
        s_mu = t / (float)HID;
    }
    __syncthreads();

    float d = v - s_mu;
    float s2 = d * d;
#pragma unroll
    for (int o = 16; o; o >>= 1) s2 += __shfl_xor_sync(0xFFFFFFFFu, s2, o);
    if ((tid & 31) == 0) red[tid >> 5] = s2;
    __syncthreads();
    if (tid == 0) {
        float t = 0.f;
#pragma unroll
        for (int i = 0; i < 8; i++) t += red[i];
        s_rs = rsqrtf(t / (float)HID + 1e-5f);
    }
    __syncthreads();

    float o = d * s_rs * g[tid] + b[tid];
    if (resid) o += resid[(size_t)row * HID + tid];
    out[(size_t)row * HID + tid] = o;
}

// ---------------------------------------------------------------------------
// Build decoder input Z[m, 0:256] = h[dec[m,0]], Z[m, 256:512] = h[dec[m,1]]
// ---------------------------------------------------------------------------
__global__ void build_Z_kernel(const int* __restrict__ dec) {
    long long idx = (long long)blockIdx.x * blockDim.x + threadIdx.x;
    long long total = (long long)M_DEC * 512;
    if (idx >= total) return;
    int m = (int)(idx >> 9);
    int k = (int)(idx & 511);
    int node = dec[m * 2 + (k >> 8)];
    g_Z[idx] = g_h[(size_t)node * HID + (k & 255)];
}

// ---------------------------------------------------------------------------
// Final tiny GEMM: out[m, 0:2] = Z2[m,:] @ w3[128,2] + b3.  One warp per row.
// ---------------------------------------------------------------------------
__global__ void final_kernel(const float* __restrict__ w3,
                             const float* __restrict__ b3,
                             float* __restrict__ out) {
    long long t = (long long)blockIdx.x * blockDim.x + threadIdx.x;
    int m = (int)(t >> 5);
    int lane = (int)(t & 31);
    if (m >= M_DEC) return;
    float4 z = *(const float4*)(g_Z2 + (size_t)m * 128 + lane * 4);
    const float* w = w3 + lane * 4 * 2;
    float s0 = z.x * w[0] + z.y * w[2] + z.z * w[4] + z.w * w[6];
    float s1 = z.x * w[1] + z.y * w[3] + z.z * w[5] + z.w * w[7];
#pragma unroll
    for (int o = 16; o; o >>= 1) {
        s0 += __shfl_xor_sync(0xFFFFFFFFu, s0, o);
        s1 += __shfl_xor_sync(0xFFFFFFFFu, s1, o);
    }
    if (lane == 0) {
        out[m * 2 + 0] = s0 + b3[0];
        out[m * 2 + 1] = s1 + b3[1];
    }
}

// ---------------------------------------------------------------------------
// Host launcher
// ---------------------------------------------------------------------------
static inline int blocks_for(long long n, int bs) { return (int)((n + bs - 1) / bs); }

extern "C" void kernel_launch(void* const* d_in, const int* in_sizes, int n_in,
                              void* d_out, int out_size) {
    const float* x     = (const float*)d_in[0];
    const int*   ei    = (const int*)  d_in[1];
    const int*   et    = (const int*)  d_in[2];
    const int*   dec   = (const int*)  d_in[3];
    const float* W1    = (const float*)d_in[4];
    const float* root1 = (const float*)d_in[5];
    const float* b1    = (const float*)d_in[6];
    const float* W2    = (const float*)d_in[7];
    const float* root2 = (const float*)d_in[8];
    const float* b2    = (const float*)d_in[9];
    const float* ln1g  = (const float*)d_in[10];
    const float* ln1b  = (const float*)d_in[11];
    const float* ln2g  = (const float*)d_in[12];
    const float* ln2b  = (const float*)d_in[13];
    const float* mw1   = (const float*)d_in[14];
    const float* mb1   = (const float*)d_in[15];
    const float* mw2   = (const float*)d_in[16];
    const float* mb2   = (const float*)d_in[17];
    const float* mw3   = (const float*)d_in[18];
    const float* mb3   = (const float*)d_in[19];
    float* out = (float*)d_out;

    float *agg, *cnt, *A, *B, *hp, *h1, *h, *Z, *Z1, *Z2;
    cudaGetSymbolAddress((void**)&agg, g_agg);
    cudaGetSymbolAddress((void**)&cnt, g_cnt);
    cudaGetSymbolAddress((void**)&A,   g_A);
    cudaGetSymbolAddress((void**)&B,   g_B);
    cudaGetSymbolAddress((void**)&hp,  g_hp);
    cudaGetSymbolAddress((void**)&h1,  g_h1);
    cudaGetSymbolAddress((void**)&h,   g_h);
    cudaGetSymbolAddress((void**)&Z,   g_Z);
    cudaGetSymbolAddress((void**)&Z1,  g_Z1);
    cudaGetSymbolAddress((void**)&Z2,  g_Z2);

    // ===================== Layer 1 (K = 128 + 8*128 = 1152) =====================
    {
        long long aggN = (long long)N_NODES * NUM_REL * IN_DIM;
        zero_kernel<<<blocks_for(aggN / 4, 256), 256>>>(agg, aggN / 4);
        zero_kernel<<<blocks_for(N_NODES * NUM_REL / 4, 256), 256>>>(cnt, N_NODES * NUM_REL / 4);

        long long aggT = (long long)E_EDGES * (IN_DIM / 4);
        aggregate_kernel<IN_DIM><<<blocks_for(aggT, 256), 256>>>(x, ei, et);

        long long aT = (long long)N_NODES * 1152;
        build_A_kernel<IN_DIM><<<blocks_for(aT, 256), 256>>>(x);
        build_B_kernel<<<blocks_for(1152 * HID, 256), 256>>>(root1, W1, IN_DIM);

        dim3 grid(HID / 128, (N_NODES + 127) / 128);
        gemm_kernel<<<grid, 256>>>(A, B, hp, b1, N_NODES, HID, 1152, 0);

        relu_ln_kernel<<<N_NODES, HID>>>(hp, ln1g, ln1b, h1, nullptr);
    }

    // ===================== Layer 2 (K = 256 + 8*256 = 2304) =====================
    {
        long long aggN = (long long)N_NODES * NUM_REL * HID;
        zero_kernel<<<blocks_for(aggN / 4, 256), 256>>>(agg, aggN / 4);
        zero_kernel<<<blocks_for(N_NODES * NUM_REL / 4, 256), 256>>>(cnt, N_NODES * NUM_REL / 4);

        long long aggT = (long long)E_EDGES * (HID / 4);
        aggregate_kernel<HID><<<blocks_for(aggT, 256), 256>>>(h1, ei, et);

        long long aT = (long long)N_NODES * 2304;
        build_A_kernel<HID><<<blocks_for(aT, 256), 256>>>(h1);
        build_B_kernel<<<blocks_for(2304 * HID, 256), 256>>>(root2, W2, HID);

        dim3 grid(HID / 128, (N_NODES + 127) / 128);
        gemm_kernel<<<grid, 256>>>(A, B, hp, b2, N_NODES, HID, 2304, 0);

        relu_ln_kernel<<<N_NODES, HID>>>(hp, ln2g, ln2b, h, h1);
    }

    // ===================== Decoder =====================
    {
        long long zT = (long long)M_DEC * 512;
        build_Z_kernel<<<blocks_for(zT, 256), 256>>>(dec);

        dim3 g1(HID / 128, (M_DEC + 127) / 128);
        gemm_kernel<<<g1, 256>>>(Z, mw1, Z1, mb1, M_DEC, HID, 2 * HID, 1);

        dim3 g2((HID / 2) / 128, (M_DEC + 127) / 128);
        gemm_kernel<<<g2, 256>>>(Z1, mw2, Z2, mb2, M_DEC, HID / 2, HID, 1);

        final_kernel<<<blocks_for((long long)M_DEC * 32, 256), 256>>>(mw3, mb3, out);
    }
}

// round 4
// speedup vs baseline: 1.0330x; 1.0319x over previous
#include <cuda_runtime.h>
#include <cstdint>
#include <cstddef>

#define N_NODES 50000
#define NUM_REL 8
#define IN_DIM  128
#define HID     256
#define E_EDGES 1600000
#define M_DEC   200000

// ---------------------------------------------------------------------------
// Device scratch (static globals — no allocation allowed)
// ---------------------------------------------------------------------------
__device__ float g_agg[(size_t)N_NODES * NUM_REL * HID];          // layer1 uses first N*8*128
__device__ float g_cnt[N_NODES * NUM_REL];
__device__ float g_A[(size_t)N_NODES * (HID + NUM_REL * HID)];    // N x 2304 (layer1: N x 1152)
__device__ float g_B[(HID + NUM_REL * HID) * HID];                // 2304 x 256
__device__ float g_hp[(size_t)N_NODES * HID];
__device__ float g_h1[(size_t)N_NODES * HID];
__device__ float g_h [(size_t)N_NODES * HID];
__device__ float g_Z [(size_t)M_DEC * 2 * HID];
__device__ float g_Z1[(size_t)M_DEC * HID];
__device__ float g_Z2[(size_t)M_DEC * (HID / 2)];

// ---------------------------------------------------------------------------
__global__ void zero_kernel(float* __restrict__ p, long long n4) {
    long long i = (long long)blockIdx.x * blockDim.x + threadIdx.x;
    if (i < n4) ((float4*)p)[i] = make_float4(0.f, 0.f, 0.f, 0.f);
}

// ---------------------------------------------------------------------------
// Edge aggregation: scatter-add feat[src] into g_agg[dst, rel, :], count edges
// ---------------------------------------------------------------------------
template <int DIM>
__global__ void aggregate_kernel(const float* __restrict__ feat,
                                 const int* __restrict__ ei,
                                 const int* __restrict__ et) {
    const int L = DIM / 4;
    long long t = (long long)blockIdx.x * blockDim.x + threadIdx.x;
    int e    = (int)(t / L);
    int lane = (int)(t % L);
    if (e >= E_EDGES) return;
    int src = ei[e];
    int dst = ei[E_EDGES + e];
    int r   = et[e];
    float4 v = *(const float4*)(feat + (size_t)src * DIM + lane * 4);
    float* dp = g_agg + ((size_t)dst * NUM_REL + r) * DIM + lane * 4;
    atomicAdd(dp + 0, v.x);
    atomicAdd(dp + 1, v.y);
    atomicAdd(dp + 2, v.z);
    atomicAdd(dp + 3, v.w);
    if (lane == 0) atomicAdd(&g_cnt[dst * NUM_REL + r], 1.0f);
}

// ---------------------------------------------------------------------------
// Build concatenated A = [feat | agg_0/cnt_0 | ... | agg_7/cnt_7]  (N x 9*DIN)
// ---------------------------------------------------------------------------
template <int DIN>
__global__ void build_A_kernel(const float* __restrict__ feat) {
    const int K = DIN * (NUM_REL + 1);
    long long idx = (long long)blockIdx.x * blockDim.x + threadIdx.x;
    long long total = (long long)N_NODES * K;
    if (idx >= total) return;
    int n = (int)(idx / K);
    int k = (int)(idx % K);
    float v;
    if (k < DIN) {
        v = feat[(size_t)n * DIN + k];
    } else {
        int r = (k - DIN) / DIN;
        int j = (k - DIN) % DIN;
        float c = g_cnt[n * NUM_REL + r];
        v = g_agg[((size_t)n * NUM_REL + r) * DIN + j] / fmaxf(c, 1.0f);
    }
    g_A[idx] = v;
}

// ---------------------------------------------------------------------------
__global__ void build_B_kernel(const float* __restrict__ root,
                               const float* __restrict__ W, int Kin) {
    int total = Kin * (NUM_REL + 1) * HID;
    int idx = blockIdx.x * blockDim.x + threadIdx.x;
    if (idx >= total) return;
    int rootN = Kin * HID;
    g_B[idx] = (idx < rootN) ? root[idx] : W[idx - rootN];
}

// ---------------------------------------------------------------------------
// TF32 tensor-core GEMM with 3xTF32 error compensation (≈fp32 accuracy).
// C[M,N] = A[M,K] @ B[K,N] + bias[N], optional exact GELU.
// 128x128 block tile, BK=16, 8 warps, warp tile 64x32 (4x4 m16n8k8 mma tiles).
// Smem holds (hi,lo) tf32 pairs as float2, row stride padded to 132 to break
// bank conflicts. Requires K % 16 == 0, N % 128 == 0 (true for all call sites).
// ---------------------------------------------------------------------------
#define GSTRIDE 132

__device__ __forceinline__ float2 tf32_split(float x) {
    uint32_t h;
    asm("cvt.rna.tf32.f32 %0, %1;" : "=r"(h) : "f"(x));
    float hf = __uint_as_float(h);
    float r = x - hf;
    uint32_t l;
    asm("cvt.rna.tf32.f32 %0, %1;" : "=r"(l) : "f"(r));
    return make_float2(hf, __uint_as_float(l));
}

#define MMA_TF32(d, a, b)                                                     \
    asm volatile("mma.sync.aligned.m16n8k8.row.col.f32.tf32.tf32.f32 "        \
                 "{%0,%1,%2,%3}, {%4,%5,%6,%7}, {%8,%9}, {%0,%1,%2,%3};"      \
                 : "+f"(d[0]), "+f"(d[1]), "+f"(d[2]), "+f"(d[3])             \
                 : "r"(a[0]), "r"(a[1]), "r"(a[2]), "r"(a[3]),                \
                   "r"(b[0]), "r"(b[1]))

__global__ __launch_bounds__(256, 2)
void gemm_tf32_kernel(const float* __restrict__ A, const float* __restrict__ B,
                      float* __restrict__ C, const float* __restrict__ bias,
                      int M, int N, int K, int act) {
    __shared__ float2 As2[16 * GSTRIDE];
    __shared__ float2 Bs2[16 * GSTRIDE];

    const int tid  = threadIdx.x;
    const int warp = tid >> 5, lane = tid & 31;
    const int gid  = lane >> 2, tig = lane & 3;
    const int wm   = (warp & 1) * 64, wn = (warp >> 1) * 32;
    const int brow = blockIdx.y * 128, bcol = blockIdx.x * 128;

    float acc[4][4][4];
#pragma unroll
    for (int i = 0; i < 4; i++)
#pragma unroll
        for (int j = 0; j < 4; j++)
#pragma unroll
            for (int c = 0; c < 4; c++) acc[i][j][c] = 0.f;

    // staging assignment
    const int arow = tid >> 1;            // 0..127
    const int akh  = (tid & 1) * 8;       // 0 or 8
    const int bkk  = tid >> 4;            // 0..15
    const int bn0  = (tid & 15) * 8;      // 0..120

    const bool arow_ok = (brow + arow) < M;
    const float* aptr = A + (size_t)(brow + arow) * K + akh;
    const float* bptr = B + (size_t)bkk * N + bcol + bn0;

    for (int k0 = 0; k0 < K; k0 += 16) {
        // ---- stage A (transposed, split to tf32 hi/lo) ----
        float4 av0 = make_float4(0.f, 0.f, 0.f, 0.f);
        float4 av1 = make_float4(0.f, 0.f, 0.f, 0.f);
        if (arow_ok) {
            av0 = *(const float4*)(aptr + k0);
            av1 = *(const float4*)(aptr + k0 + 4);
        }
        {
            float a[8] = {av0.x, av0.y, av0.z, av0.w, av1.x, av1.y, av1.z, av1.w};
#pragma unroll
            for (int i = 0; i < 8; i++)
                As2[(akh + i) * GSTRIDE + arow] = tf32_split(a[i]);
        }
        // ---- stage B (split to tf32 hi/lo) ----
        {
            float4 bv0 = *(const float4*)(bptr + (size_t)k0 * N);
            float4 bv1 = *(const float4*)(bptr + (size_t)k0 * N + 4);
            float b[8] = {bv0.x, bv0.y, bv0.z, bv0.w, bv1.x, bv1.y, bv1.z, bv1.w};
            float2* dst = &Bs2[bkk * GSTRIDE + bn0];
#pragma unroll
            for (int i = 0; i < 8; i++) dst[i] = tf32_split(b[i]);
        }
        __syncthreads();

        // ---- compute: two k=8 steps ----
#pragma unroll
        for (int ks = 0; ks < 16; ks += 8) {
            uint32_t bh[4][2], bl[4][2];
#pragma unroll
            for (int nt = 0; nt < 4; nt++) {
                float2 b0 = Bs2[(ks + tig) * GSTRIDE + wn + nt * 8 + gid];
                float2 b1 = Bs2[(ks + tig + 4) * GSTRIDE + wn + nt * 8 + gid];
                bh[nt][0] = __float_as_uint(b0.x);
                bl[nt][0] = __float_as_uint(b0.y);
                bh[nt][1] = __float_as_uint(b1.x);
                bl[nt][1] = __float_as_uint(b1.y);
            }
#pragma unroll
            for (int mt = 0; mt < 4; mt++) {
                int m0 = wm + mt * 16 + gid;
                float2 a0 = As2[(ks + tig) * GSTRIDE + m0];
                float2 a1 = As2[(ks + tig) * GSTRIDE + m0 + 8];
                float2 a2 = As2[(ks + tig + 4) * GSTRIDE + m0];
                float2 a3 = As2[(ks + tig + 4) * GSTRIDE + m0 + 8];
                uint32_t ah[4] = {__float_as_uint(a0.x), __float_as_uint(a1.x),
                                  __float_as_uint(a2.x), __float_as_uint(a3.x)};
                uint32_t al[4] = {__float_as_uint(a0.y), __float_as_uint(a1.y),
                                  __float_as_uint(a2.y), __float_as_uint(a3.y)};
#pragma unroll
                for (int nt = 0; nt < 4; nt++) {
                    MMA_TF32(acc[mt][nt], ah, bh[nt]);   // hi*hi
                    MMA_TF32(acc[mt][nt], ah, bl[nt]);   // hi*lo
                    MMA_TF32(acc[mt][nt], al, bh[nt]);   // lo*hi
                }
            }
        }
        __syncthreads();
    }

    // ---- epilogue: bias (+ exact GELU), guarded float2 stores ----
#pragma unroll
    for (int mt = 0; mt < 4; mt++) {
        int r0 = brow + wm + mt * 16 + gid;
#pragma unroll
        for (int nt = 0; nt < 4; nt++) {
            int c = bcol + wn + nt * 8 + 2 * tig;
            float bb0 = bias[c], bb1 = bias[c + 1];
            float v0 = acc[mt][nt][0] + bb0;
            float v1 = acc[mt][nt][1] + bb1;
            float v2 = acc[mt][nt][2] + bb0;
            float v3 = acc[mt][nt][3] + bb1;
            if (act == 1) {
                const float is2 = 0.70710678118654752f;
                v0 = 0.5f * v0 * (1.0f + erff(v0 * is2));
                v1 = 0.5f * v1 * (1.0f + erff(v1 * is2));
                v2 = 0.5f * v2 * (1.0f + erff(v2 * is2));
                v3 = 0.5f * v3 * (1.0f + erff(v3 * is2));
            }
            if (r0 < M)
                *(float2*)(C + (size_t)r0 * N + c) = make_float2(v0, v1);
            if (r0 + 8 < M)
                *(float2*)(C + (size_t)(r0 + 8) * N + c) = make_float2(v2, v3);
        }
    }
}

// ---------------------------------------------------------------------------
// Row-wise ReLU + LayerNorm (+ optional residual): out = resid + LN(relu(hp))
// ---------------------------------------------------------------------------
__global__ void relu_ln_kernel(const float* __restrict__ hp,
                               const float* __restrict__ g,
                               const float* __restrict__ b,
                               float* __restrict__ out,
                               const float* __restrict__ resid) {
    int row = blockIdx.x;
    int tid = threadIdx.x;   // 256 == HID
    float v = fmaxf(hp[(size_t)row * HID + tid], 0.0f);

    __shared__ float red[8];
    __shared__ float s_mu, s_rs;

    float s = v;
#pragma unroll
    for (int o = 16; o; o >>= 1) s += __shfl_xor_sync(0xFFFFFFFFu, s, o);
    if ((tid & 31) == 0) red[tid >> 5] = s;
    __syncthreads();
    if (tid == 0) {
        float t = 0.f;
#pragma unroll
        for (int i = 0; i < 8; i++) t += red[i];
        s_mu = t / (float)HID;
    }
    __syncthreads();

    float d = v - s_mu;
    float s2 = d * d;
#pragma unroll
    for (int o = 16; o; o >>= 1) s2 += __shfl_xor_sync(0xFFFFFFFFu, s2, o);
    if ((tid & 31) == 0) red[tid >> 5] = s2;
    __syncthreads();
    if (tid == 0) {
        float t = 0.f;
#pragma unroll
        for (int i = 0; i < 8; i++) t += red[i];
        s_rs = rsqrtf(t / (float)HID + 1e-5f);
    }
    __syncthreads();

    float o = d * s_rs * g[tid] + b[tid];
    if (resid) o += resid[(size_t)row * HID + tid];
    out[(size_t)row * HID + tid] = o;
}

// ---------------------------------------------------------------------------
__global__ void build_Z_kernel(const int* __restrict__ dec) {
    long long idx = (long long)blockIdx.x * blockDim.x + threadIdx.x;
    long long total = (long long)M_DEC * 512;
    if (idx >= total) return;
    int m = (int)(idx >> 9);
    int k = (int)(idx & 511);
    int node = dec[m * 2 + (k >> 8)];
    g_Z[idx] = g_h[(size_t)node * HID + (k & 255)];
}

// ---------------------------------------------------------------------------
__global__ void final_kernel(const float* __restrict__ w3,
                             const float* __restrict__ b3,
                             float* __restrict__ out) {
    long long t = (long long)blockIdx.x * blockDim.x + threadIdx.x;
    int m = (int)(t >> 5);
    int lane = (int)(t & 31);
    if (m >= M_DEC) return;
    float4 z = *(const float4*)(g_Z2 + (size_t)m * 128 + lane * 4);
    const float* w = w3 + lane * 4 * 2;
    float s0 = z.x * w[0] + z.y * w[2] + z.z * w[4] + z.w * w[6];
    float s1 = z.x * w[1] + z.y * w[3] + z.z * w[5] + z.w * w[7];
#pragma unroll
    for (int o = 16; o; o >>= 1) {
        s0 += __shfl_xor_sync(0xFFFFFFFFu, s0, o);
        s1 += __shfl_xor_sync(0xFFFFFFFFu, s1, o);
    }
    if (lane == 0) {
        out[m * 2 + 0] = s0 + b3[0];
        out[m * 2 + 1] = s1 + b3[1];
    }
}

// ---------------------------------------------------------------------------
static inline int blocks_for(long long n, int bs) { return (int)((n + bs - 1) / bs); }

extern "C" void kernel_launch(void* const* d_in, const int* in_sizes, int n_in,
                              void* d_out, int out_size) {
    const float* x     = (const float*)d_in[0];
    const int*   ei    = (const int*)  d_in[1];
    const int*   et    = (const int*)  d_in[2];
    const int*   dec   = (const int*)  d_in[3];
    const float* W1    = (const float*)d_in[4];
    const float* root1 = (const float*)d_in[5];
    const float* b1    = (const float*)d_in[6];
    const float* W2    = (const float*)d_in[7];
    const float* root2 = (const float*)d_in[8];
    const float* b2    = (const float*)d_in[9];
    const float* ln1g  = (const float*)d_in[10];
    const float* ln1b  = (const float*)d_in[11];
    const float* ln2g  = (const float*)d_in[12];
    const float* ln2b  = (const float*)d_in[13];
    const float* mw1   = (const float*)d_in[14];
    const float* mb1   = (const float*)d_in[15];
    const float* mw2   = (const float*)d_in[16];
    const float* mb2   = (const float*)d_in[17];
    const float* mw3   = (const float*)d_in[18];
    const float* mb3   = (const float*)d_in[19];
    float* out = (float*)d_out;

    float *agg, *cnt, *A, *B, *hp, *h1, *h, *Z, *Z1, *Z2;
    cudaGetSymbolAddress((void**)&agg, g_agg);
    cudaGetSymbolAddress((void**)&cnt, g_cnt);
    cudaGetSymbolAddress((void**)&A,   g_A);
    cudaGetSymbolAddress((void**)&B,   g_B);
    cudaGetSymbolAddress((void**)&hp,  g_hp);
    cudaGetSymbolAddress((void**)&h1,  g_h1);
    cudaGetSymbolAddress((void**)&h,   g_h);
    cudaGetSymbolAddress((void**)&Z,   g_Z);
    cudaGetSymbolAddress((void**)&Z1,  g_Z1);
    cudaGetSymbolAddress((void**)&Z2,  g_Z2);

    // ===================== Layer 1 (K = 1152) =====================
    {
        long long aggN = (long long)N_NODES * NUM_REL * IN_DIM;
        zero_kernel<<<blocks_for(aggN / 4, 256), 256>>>(agg, aggN / 4);
        zero_kernel<<<blocks_for(N_NODES * NUM_REL / 4, 256), 256>>>(cnt, N_NODES * NUM_REL / 4);

        long long aggT = (long long)E_EDGES * (IN_DIM / 4);
        aggregate_kernel<IN_DIM><<<blocks_for(aggT, 256), 256>>>(x, ei, et);

        long long aT = (long long)N_NODES * 1152;
        build_A_kernel<IN_DIM><<<blocks_for(aT, 256), 256>>>(x);
        build_B_kernel<<<blocks_for(1152 * HID, 256), 256>>>(root1, W1, IN_DIM);

        dim3 grid(HID / 128, (N_NODES + 127) / 128);
        gemm_tf32_kernel<<<grid, 256>>>(A, B, hp, b1, N_NODES, HID, 1152, 0);

        relu_ln_kernel<<<N_NODES, HID>>>(hp, ln1g, ln1b, h1, nullptr);
    }

    // ===================== Layer 2 (K = 2304) =====================
    {
        long long aggN = (long long)N_NODES * NUM_REL * HID;
        zero_kernel<<<blocks_for(aggN / 4, 256), 256>>>(agg, aggN / 4);
        zero_kernel<<<blocks_for(N_NODES * NUM_REL / 4, 256), 256>>>(cnt, N_NODES * NUM_REL / 4);

        long long aggT = (long long)E_EDGES * (HID / 4);
        aggregate_kernel<HID><<<blocks_for(aggT, 256), 256>>>(h1, ei, et);

        long long aT = (long long)N_NODES * 2304;
        build_A_kernel<HID><<<blocks_for(aT, 256), 256>>>(h1);
        build_B_kernel<<<blocks_for(2304 * HID, 256), 256>>>(root2, W2, HID);

        dim3 grid(HID / 128, (N_NODES + 127) / 128);
        gemm_tf32_kernel<<<grid, 256>>>(A, B, hp, b2, N_NODES, HID, 2304, 0);

        relu_ln_kernel<<<N_NODES, HID>>>(hp, ln2g, ln2b, h, h1);
    }

    // ===================== Decoder =====================
    {
        long long zT = (long long)M_DEC * 512;
        build_Z_kernel<<<blocks_for(zT, 256), 256>>>(dec);

        dim3 g1(HID / 128, (M_DEC + 127) / 128);
        gemm_tf32_kernel<<<g1, 256>>>(Z, mw1, Z1, mb1, M_DEC, HID, 2 * HID, 1);

        dim3 g2((HID / 2) / 128, (M_DEC + 127) / 128);
        gemm_tf32_kernel<<<g2, 256>>>(Z1, mw2, Z2, mb2, M_DEC, HID / 2, HID, 1);

        final_kernel<<<blocks_for((long long)M_DEC * 32, 256), 256>>>(mw3, mb3, out);
    }
}

// round 5
// speedup vs baseline: 1.4284x; 1.3828x over previous
#include <cuda_runtime.h>
#include <cstdint>
#include <cstddef>

#define N_NODES 50000
#define NUM_REL 8
#define IN_DIM  128
#define HID     256
#define E_EDGES 1600000
#define M_DEC   200000
#define NKEYS   (N_NODES * NUM_REL)      // 400000

// ---------------------------------------------------------------------------
// Device scratch (static globals — no allocation allowed)
// ---------------------------------------------------------------------------
__device__ int   g_deg[NKEYS];
__device__ int   g_off[NKEYS];
__device__ int   g_cur[NKEYS];
__device__ int   g_srcs[E_EDGES];
__device__ int   g_bsums[512];
__device__ float g_A[(size_t)N_NODES * (HID + NUM_REL * HID)];    // N x 2304 (layer1: N x 1152)
__device__ float g_B[(HID + NUM_REL * HID) * HID];                // 2304 x 256
__device__ float g_hp[(size_t)N_NODES * HID];
__device__ float g_h1[(size_t)N_NODES * HID];
__device__ float g_h [(size_t)N_NODES * HID];
__device__ float g_Z [(size_t)M_DEC * 2 * HID];
__device__ float g_Z1[(size_t)M_DEC * HID];
__device__ float g_Z2[(size_t)M_DEC * (HID / 2)];

// ---------------------------------------------------------------------------
__global__ void zero_int_kernel(int* __restrict__ p, int n4) {
    int i = blockIdx.x * blockDim.x + threadIdx.x;
    if (i < n4) ((int4*)p)[i] = make_int4(0, 0, 0, 0);
}

// ---------------------------------------------------------------------------
// CSR build over keys (dst*8 + rel)
// ---------------------------------------------------------------------------
__global__ void hist_kernel(const int* __restrict__ ei, const int* __restrict__ et) {
    int e = blockIdx.x * blockDim.x + threadIdx.x;
    if (e >= E_EDGES) return;
    int key = ei[E_EDGES + e] * NUM_REL + et[e];
    atomicAdd(&g_deg[key], 1);
}

// Block-level exclusive scan: 256 threads x 4 elems = 1024 per block.
__global__ void scan1_kernel(const int* __restrict__ in, int* __restrict__ out, int n) {
    __shared__ int s[256];
    int t = threadIdx.x;
    int base = blockIdx.x * 1024 + t * 4;
    int v0 = 0, v1 = 0, v2 = 0, v3 = 0;
    if (base + 0 < n) v0 = in[base + 0];
    if (base + 1 < n) v1 = in[base + 1];
    if (base + 2 < n) v2 = in[base + 2];
    if (base + 3 < n) v3 = in[base + 3];
    int tsum = v0 + v1 + v2 + v3;
    s[t] = tsum;
    __syncthreads();
    for (int o = 1; o < 256; o <<= 1) {
        int x = (t >= o) ? s[t - o] : 0;
        __syncthreads();
        s[t] += x;
        __syncthreads();
    }
    int excl = s[t] - tsum;
    if (t == 255) g_bsums[blockIdx.x] = s[255];
    if (base + 0 < n) out[base + 0] = excl;
    if (base + 1 < n) out[base + 1] = excl + v0;
    if (base + 2 < n) out[base + 2] = excl + v0 + v1;
    if (base + 3 < n) out[base + 3] = excl + v0 + v1 + v2;
}

__global__ void scan2_kernel(int nb) {
    __shared__ int s[512];
    int t = threadIdx.x;
    int v = (t < nb) ? g_bsums[t] : 0;
    s[t] = v;
    __syncthreads();
    for (int o = 1; o < 512; o <<= 1) {
        int x = (t >= o) ? s[t - o] : 0;
        __syncthreads();
        s[t] += x;
        __syncthreads();
    }
    if (t < nb) g_bsums[t] = s[t] - v;   // exclusive
}

__global__ void scan3_kernel(int* __restrict__ off, int* __restrict__ cur, int n) {
    int i = blockIdx.x * blockDim.x + threadIdx.x;
    if (i >= n) return;
    int o = off[i] + g_bsums[i >> 10];
    off[i] = o;
    cur[i] = o;
}

__global__ void fill_kernel(const int* __restrict__ ei, const int* __restrict__ et) {
    int e = blockIdx.x * blockDim.x + threadIdx.x;
    if (e >= E_EDGES) return;
    int key = ei[E_EDGES + e] * NUM_REL + et[e];
    int p = atomicAdd(&g_cur[key], 1);
    g_srcs[p] = ei[e];
}

// ---------------------------------------------------------------------------
// Gather-reduce aggregation: one warp per (node, rel) key. Sums feat[src] over
// the key's CSR edge list and writes the normalized mean directly into
// g_A[n, (1+r)*DIN : (2+r)*DIN].  No float atomics, no pre-zeroing.
// ---------------------------------------------------------------------------
template <int DIN>
__global__ void gather_agg_kernel(const float* __restrict__ feat) {
    const int K = DIN * (NUM_REL + 1);
    int w = (blockIdx.x * blockDim.x + threadIdx.x) >> 5;
    int lane = threadIdx.x & 31;
    if (w >= NKEYS) return;
    int n = w >> 3;
    int r = w & 7;
    int off = g_off[w];
    int cnt = g_deg[w];

    float4 a0 = make_float4(0.f, 0.f, 0.f, 0.f);
    float4 a1 = make_float4(0.f, 0.f, 0.f, 0.f);

    int i = 0;
    for (; i + 2 <= cnt; i += 2) {
        int s0 = g_srcs[off + i];
        int s1 = g_srcs[off + i + 1];
        const float4* p0 = (const float4*)(feat + (size_t)s0 * DIN) + lane;
        const float4* p1 = (const float4*)(feat + (size_t)s1 * DIN) + lane;
        float4 v0 = __ldg(p0);
        float4 v1 = __ldg(p1);
        float4 u0, u1;
        if (DIN == 256) { u0 = __ldg(p0 + 32); u1 = __ldg(p1 + 32); }
        a0.x += v0.x + v1.x; a0.y += v0.y + v1.y;
        a0.z += v0.z + v1.z; a0.w += v0.w + v1.w;
        if (DIN == 256) {
            a1.x += u0.x + u1.x; a1.y += u0.y + u1.y;
            a1.z += u0.z + u1.z; a1.w += u0.w + u1.w;
        }
    }
    if (i < cnt) {
        int s0 = g_srcs[off + i];
        const float4* p0 = (const float4*)(feat + (size_t)s0 * DIN) + lane;
        float4 v0 = __ldg(p0);
        a0.x += v0.x; a0.y += v0.y; a0.z += v0.z; a0.w += v0.w;
        if (DIN == 256) {
            float4 u0 = __ldg(p0 + 32);
            a1.x += u0.x; a1.y += u0.y; a1.z += u0.z; a1.w += u0.w;
        }
    }

    float sc = 1.0f / fmaxf((float)cnt, 1.0f);
    a0.x *= sc; a0.y *= sc; a0.z *= sc; a0.w *= sc;
    float4* dst = (float4*)(g_A + (size_t)n * K + (1 + r) * DIN) + lane;
    *dst = a0;
    if (DIN == 256) {
        a1.x *= sc; a1.y *= sc; a1.z *= sc; a1.w *= sc;
        *(dst + 32) = a1;
    }
}

// Copy node features into A[:, 0:DIN]
template <int DIN>
__global__ void copy_feat_kernel(const float* __restrict__ feat) {
    const int K = DIN * (NUM_REL + 1);
    const int L = DIN / 4;
    int idx = blockIdx.x * blockDim.x + threadIdx.x;
    if (idx >= N_NODES * L) return;
    int n = idx / L;
    int j = idx % L;
    *((float4*)(g_A + (size_t)n * K) + j) = *((const float4*)(feat + (size_t)n * DIN) + j);
}

// ---------------------------------------------------------------------------
__global__ void build_B_kernel(const float* __restrict__ root,
                               const float* __restrict__ W, int Kin) {
    int total = Kin * (NUM_REL + 1) * HID;
    int idx = blockIdx.x * blockDim.x + threadIdx.x;
    if (idx >= total) return;
    int rootN = Kin * HID;
    g_B[idx] = (idx < rootN) ? root[idx] : W[idx - rootN];
}

// ---------------------------------------------------------------------------
// TF32 tensor-core GEMM with 3xTF32 error compensation (unchanged from R3).
// ---------------------------------------------------------------------------
#define GSTRIDE 132

__device__ __forceinline__ float2 tf32_split(float x) {
    uint32_t h;
    asm("cvt.rna.tf32.f32 %0, %1;" : "=r"(h) : "f"(x));
    float hf = __uint_as_float(h);
    float r = x - hf;
    uint32_t l;
    asm("cvt.rna.tf32.f32 %0, %1;" : "=r"(l) : "f"(r));
    return make_float2(hf, __uint_as_float(l));
}

#define MMA_TF32(d, a, b)                                                     \
    asm volatile("mma.sync.aligned.m16n8k8.row.col.f32.tf32.tf32.f32 "        \
                 "{%0,%1,%2,%3}, {%4,%5,%6,%7}, {%8,%9}, {%0,%1,%2,%3};"      \
                 : "+f"(d[0]), "+f"(d[1]), "+f"(d[2]), "+f"(d[3])             \
                 : "r"(a[0]), "r"(a[1]), "r"(a[2]), "r"(a[3]),                \
                   "r"(b[0]), "r"(b[1]))

__global__ __launch_bounds__(256, 2)
void gemm_tf32_kernel(const float* __restrict__ A, const float* __restrict__ B,
                      float* __restrict__ C, const float* __restrict__ bias,
                      int M, int N, int K, int act) {
    __shared__ float2 As2[16 * GSTRIDE];
    __shared__ float2 Bs2[16 * GSTRIDE];

    const int tid  = threadIdx.x;
    const int warp = tid >> 5, lane = tid & 31;
    const int gid  = lane >> 2, tig = lane & 3;
    const int wm   = (warp & 1) * 64, wn = (warp >> 1) * 32;
    const int brow = blockIdx.y * 128, bcol = blockIdx.x * 128;

    float acc[4][4][4];
#pragma unroll
    for (int i = 0; i < 4; i++)
#pragma unroll
        for (int j = 0; j < 4; j++)
#pragma unroll
            for (int c = 0; c < 4; c++) acc[i][j][c] = 0.f;

    const int arow = tid >> 1;
    const int akh  = (tid & 1) * 8;
    const int bkk  = tid >> 4;
    const int bn0  = (tid & 15) * 8;

    const bool arow_ok = (brow + arow) < M;
    const float* aptr = A + (size_t)(brow + arow) * K + akh;
    const float* bptr = B + (size_t)bkk * N + bcol + bn0;

    for (int k0 = 0; k0 < K; k0 += 16) {
        float4 av0 = make_float4(0.f, 0.f, 0.f, 0.f);
        float4 av1 = make_float4(0.f, 0.f, 0.f, 0.f);
        if (arow_ok) {
            av0 = *(const float4*)(aptr + k0);
            av1 = *(const float4*)(aptr + k0 + 4);
        }
        {
            float a[8] = {av0.x, av0.y, av0.z, av0.w, av1.x, av1.y, av1.z, av1.w};
#pragma unroll
            for (int i = 0; i < 8; i++)
                As2[(akh + i) * GSTRIDE + arow] = tf32_split(a[i]);
        }
        {
            float4 bv0 = *(const float4*)(bptr + (size_t)k0 * N);
            float4 bv1 = *(const float4*)(bptr + (size_t)k0 * N + 4);
            float b[8] = {bv0.x, bv0.y, bv0.z, bv0.w, bv1.x, bv1.y, bv1.z, bv1.w};
            float2* dst = &Bs2[bkk * GSTRIDE + bn0];
#pragma unroll
            for (int i = 0; i < 8; i++) dst[i] = tf32_split(b[i]);
        }
        __syncthreads();

#pragma unroll
        for (int ks = 0; ks < 16; ks += 8) {
            uint32_t bh[4][2], bl[4][2];
#pragma unroll
            for (int nt = 0; nt < 4; nt++) {
                float2 b0 = Bs2[(ks + tig) * GSTRIDE + wn + nt * 8 + gid];
                float2 b1 = Bs2[(ks + tig + 4) * GSTRIDE + wn + nt * 8 + gid];
                bh[nt][0] = __float_as_uint(b0.x);
                bl[nt][0] = __float_as_uint(b0.y);
                bh[nt][1] = __float_as_uint(b1.x);
                bl[nt][1] = __float_as_uint(b1.y);
            }
#pragma unroll
            for (int mt = 0; mt < 4; mt++) {
                int m0 = wm + mt * 16 + gid;
                float2 a0 = As2[(ks + tig) * GSTRIDE + m0];
                float2 a1 = As2[(ks + tig) * GSTRIDE + m0 + 8];
                float2 a2 = As2[(ks + tig + 4) * GSTRIDE + m0];
                float2 a3 = As2[(ks + tig + 4) * GSTRIDE + m0 + 8];
                uint32_t ah[4] = {__float_as_uint(a0.x), __float_as_uint(a1.x),
                                  __float_as_uint(a2.x), __float_as_uint(a3.x)};
                uint32_t al[4] = {__float_as_uint(a0.y), __float_as_uint(a1.y),
                                  __float_as_uint(a2.y), __float_as_uint(a3.y)};
#pragma unroll
                for (int nt = 0; nt < 4; nt++) {
                    MMA_TF32(acc[mt][nt], ah, bh[nt]);
                    MMA_TF32(acc[mt][nt], ah, bl[nt]);
                    MMA_TF32(acc[mt][nt], al, bh[nt]);
                }
            }
        }
        __syncthreads();
    }

#pragma unroll
    for (int mt = 0; mt < 4; mt++) {
        int r0 = brow + wm + mt * 16 + gid;
#pragma unroll
        for (int nt = 0; nt < 4; nt++) {
            int c = bcol + wn + nt * 8 + 2 * tig;
            float bb0 = bias[c], bb1 = bias[c + 1];
            float v0 = acc[mt][nt][0] + bb0;
            float v1 = acc[mt][nt][1] + bb1;
            float v2 = acc[mt][nt][2] + bb0;
            float v3 = acc[mt][nt][3] + bb1;
            if (act == 1) {
                const float is2 = 0.70710678118654752f;
                v0 = 0.5f * v0 * (1.0f + erff(v0 * is2));
                v1 = 0.5f * v1 * (1.0f + erff(v1 * is2));
                v2 = 0.5f * v2 * (1.0f + erff(v2 * is2));
                v3 = 0.5f * v3 * (1.0f + erff(v3 * is2));
            }
            if (r0 < M)
                *(float2*)(C + (size_t)r0 * N + c) = make_float2(v0, v1);
            if (r0 + 8 < M)
                *(float2*)(C + (size_t)(r0 + 8) * N + c) = make_float2(v2, v3);
        }
    }
}

// ---------------------------------------------------------------------------
__global__ void relu_ln_kernel(const float* __restrict__ hp,
                               const float* __restrict__ g,
                               const float* __restrict__ b,
                               float* __restrict__ out,
                               const float* __restrict__ resid) {
    int row = blockIdx.x;
    int tid = threadIdx.x;   // 256 == HID
    float v = fmaxf(hp[(size_t)row * HID + tid], 0.0f);

    __shared__ float red[8];
    __shared__ float s_mu, s_rs;

    float s = v;
#pragma unroll
    for (int o = 16; o; o >>= 1) s += __shfl_xor_sync(0xFFFFFFFFu, s, o);
    if ((tid & 31) == 0) red[tid >> 5] = s;
    __syncthreads();
    if (tid == 0) {
        float t = 0.f;
#pragma unroll
        for (int i = 0; i < 8; i++) t += red[i];
        s_mu = t / (float)HID;
    }
    __syncthreads();

    float d = v - s_mu;
    float s2 = d * d;
#pragma unroll
    for (int o = 16; o; o >>= 1) s2 += __shfl_xor_sync(0xFFFFFFFFu, s2, o);
    if ((tid & 31) == 0) red[tid >> 5] = s2;
    __syncthreads();
    if (tid == 0) {
        float t = 0.f;
#pragma unroll
        for (int i = 0; i < 8; i++) t += red[i];
        s_rs = rsqrtf(t / (float)HID + 1e-5f);
    }
    __syncthreads();

    float o = d * s_rs * g[tid] + b[tid];
    if (resid) o += resid[(size_t)row * HID + tid];
    out[(size_t)row * HID + tid] = o;
}

// ---------------------------------------------------------------------------
__global__ void build_Z_kernel(const int* __restrict__ dec) {
    long long idx = (long long)blockIdx.x * blockDim.x + threadIdx.x;
    long long total = (long long)M_DEC * 512;
    if (idx >= total) return;
    int m = (int)(idx >> 9);
    int k = (int)(idx & 511);
    int node = dec[m * 2 + (k >> 8)];
    g_Z[idx] = g_h[(size_t)node * HID + (k & 255)];
}

// ---------------------------------------------------------------------------
__global__ void final_kernel(const float* __restrict__ w3,
                             const float* __restrict__ b3,
                             float* __restrict__ out) {
    long long t = (long long)blockIdx.x * blockDim.x + threadIdx.x;
    int m = (int)(t >> 5);
    int lane = (int)(t & 31);
    if (m >= M_DEC) return;
    float4 z = *(const float4*)(g_Z2 + (size_t)m * 128 + lane * 4);
    const float* w = w3 + lane * 4 * 2;
    float s0 = z.x * w[0] + z.y * w[2] + z.z * w[4] + z.w * w[6];
    float s1 = z.x * w[1] + z.y * w[3] + z.z * w[5] + z.w * w[7];
#pragma unroll
    for (int o = 16; o; o >>= 1) {
        s0 += __shfl_xor_sync(0xFFFFFFFFu, s0, o);
        s1 += __shfl_xor_sync(0xFFFFFFFFu, s1, o);
    }
    if (lane == 0) {
        out[m * 2 + 0] = s0 + b3[0];
        out[m * 2 + 1] = s1 + b3[1];
    }
}

// ---------------------------------------------------------------------------
static inline int blocks_for(long long n, int bs) { return (int)((n + bs - 1) / bs); }

extern "C" void kernel_launch(void* const* d_in, const int* in_sizes, int n_in,
                              void* d_out, int out_size) {
    const float* x     = (const float*)d_in[0];
    const int*   ei    = (const int*)  d_in[1];
    const int*   et    = (const int*)  d_in[2];
    const int*   dec   = (const int*)  d_in[3];
    const float* W1    = (const float*)d_in[4];
    const float* root1 = (const float*)d_in[5];
    const float* b1    = (const float*)d_in[6];
    const float* W2    = (const float*)d_in[7];
    const float* root2 = (const float*)d_in[8];
    const float* b2    = (const float*)d_in[9];
    const float* ln1g  = (const float*)d_in[10];
    const float* ln1b  = (const float*)d_in[11];
    const float* ln2g  = (const float*)d_in[12];
    const float* ln2b  = (const float*)d_in[13];
    const float* mw1   = (const float*)d_in[14];
    const float* mb1   = (const float*)d_in[15];
    const float* mw2   = (const float*)d_in[16];
    const float* mb2   = (const float*)d_in[17];
    const float* mw3   = (const float*)d_in[18];
    const float* mb3   = (const float*)d_in[19];
    float* out = (float*)d_out;

    float *A, *B, *hp, *h1, *h;
    int *deg, *off, *cur;
    cudaGetSymbolAddress((void**)&A,   g_A);
    cudaGetSymbolAddress((void**)&B,   g_B);
    cudaGetSymbolAddress((void**)&hp,  g_hp);
    cudaGetSymbolAddress((void**)&h1,  g_h1);
    cudaGetSymbolAddress((void**)&h,   g_h);
    cudaGetSymbolAddress((void**)&deg, g_deg);
    cudaGetSymbolAddress((void**)&off, g_off);
    cudaGetSymbolAddress((void**)&cur, g_cur);
    float *Z, *Z1, *Z2;
    cudaGetSymbolAddress((void**)&Z,   g_Z);
    cudaGetSymbolAddress((void**)&Z1,  g_Z1);
    cudaGetSymbolAddress((void**)&Z2,  g_Z2);

    // ===================== CSR build (shared by both layers) =====================
    {
        zero_int_kernel<<<blocks_for(NKEYS / 4, 256), 256>>>(deg, NKEYS / 4);
        hist_kernel<<<blocks_for(E_EDGES, 256), 256>>>(ei, et);
        int nblk = (NKEYS + 1023) / 1024;     // 391
        scan1_kernel<<<nblk, 256>>>(deg, off, NKEYS);
        scan2_kernel<<<1, 512>>>(nblk);
        scan3_kernel<<<blocks_for(NKEYS, 256), 256>>>(off, cur, NKEYS);
        fill_kernel<<<blocks_for(E_EDGES, 256), 256>>>(ei, et);
    }

    // ===================== Layer 1 (K = 1152) =====================
    {
        copy_feat_kernel<IN_DIM><<<blocks_for(N_NODES * (IN_DIM / 4), 256), 256>>>(x);
        gather_agg_kernel<IN_DIM><<<blocks_for((long long)NKEYS * 32, 256), 256>>>(x);
        build_B_kernel<<<blocks_for(1152 * HID, 256), 256>>>(root1, W1, IN_DIM);

        dim3 grid(HID / 128, (N_NODES + 127) / 128);
        gemm_tf32_kernel<<<grid, 256>>>(A, B, hp, b1, N_NODES, HID, 1152, 0);

        relu_ln_kernel<<<N_NODES, HID>>>(hp, ln1g, ln1b, h1, nullptr);
    }

    // ===================== Layer 2 (K = 2304) =====================
    {
        copy_feat_kernel<HID><<<blocks_for(N_NODES * (HID / 4), 256), 256>>>(h1);
        gather_agg_kernel<HID><<<blocks_for((long long)NKEYS * 32, 256), 256>>>(h1);
        build_B_kernel<<<blocks_for(2304 * HID, 256), 256>>>(root2, W2, HID);

        dim3 grid(HID / 128, (N_NODES + 127) / 128);
        gemm_tf32_kernel<<<grid, 256>>>(A, B, hp, b2, N_NODES, HID, 2304, 0);

        relu_ln_kernel<<<N_NODES, HID>>>(hp, ln2g, ln2b, h, h1);
    }

    // ===================== Decoder =====================
    {
        long long zT = (long long)M_DEC * 512;
        build_Z_kernel<<<blocks_for(zT, 256), 256>>>(dec);

        dim3 g1(HID / 128, (M_DEC + 127) / 128);
        gemm_tf32_kernel<<<g1, 256>>>(Z, mw1, Z1, mb1, M_DEC, HID, 2 * HID, 1);

        dim3 g2((HID / 2) / 128, (M_DEC + 127) / 128);
        gemm_tf32_kernel<<<g2, 256>>>(Z1, mw2, Z2, mb2, M_DEC, HID / 2, HID, 1);

        final_kernel<<<blocks_for((long long)M_DEC * 32, 256), 256>>>(mw3, mb3, out);
    }
}

// round 6
// speedup vs baseline: 3.2629x; 2.2842x over previous
#include <cuda_runtime.h>
#include <cuda_bf16.h>
#include <cstdint>
#include <cstddef>

#define N_NODES 50000
#define NUM_REL 8
#define IN_DIM  128
#define HID     256
#define E_EDGES 1600000
#define M_DEC   200000
#define NKEYS   (N_NODES * NUM_REL)      // 400000

// ---------------------------------------------------------------------------
// Device scratch (static globals — no allocation allowed)
// ---------------------------------------------------------------------------
__device__ int   g_deg[NKEYS];
__device__ int   g_off[NKEYS];
__device__ int   g_cur[NKEYS];
__device__ int   g_srcs[E_EDGES];
__device__ int   g_bsums[512];
__device__ float g_A[(size_t)N_NODES * (HID + NUM_REL * HID)];    // N x 2304 (layer1: N x 1152)
__device__ float g_B[(HID + NUM_REL * HID) * HID];                // 2304 x 256 (also 256x512 dec)
__device__ float g_hp[(size_t)N_NODES * HID];
__device__ float g_h1[(size_t)N_NODES * HID];
__device__ float g_h [(size_t)N_NODES * HID];
__device__ float g_P [(size_t)N_NODES * 2 * HID];                 // 50000 x 512
__device__ float g_Z1[(size_t)M_DEC * HID];
__device__ float g_Z2[(size_t)M_DEC * (HID / 2)];

// ---------------------------------------------------------------------------
__global__ void zero_int_kernel(int* __restrict__ p, int n4) {
    int i = blockIdx.x * blockDim.x + threadIdx.x;
    if (i < n4) ((int4*)p)[i] = make_int4(0, 0, 0, 0);
}

// ---------------------------------------------------------------------------
// CSR build over keys (dst*8 + rel)
// ---------------------------------------------------------------------------
__global__ void hist_kernel(const int* __restrict__ ei, const int* __restrict__ et) {
    int e = blockIdx.x * blockDim.x + threadIdx.x;
    if (e >= E_EDGES) return;
    int key = ei[E_EDGES + e] * NUM_REL + et[e];
    atomicAdd(&g_deg[key], 1);
}

__global__ void scan1_kernel(const int* __restrict__ in, int* __restrict__ out, int n) {
    __shared__ int s[256];
    int t = threadIdx.x;
    int base = blockIdx.x * 1024 + t * 4;
    int v0 = 0, v1 = 0, v2 = 0, v3 = 0;
    if (base + 0 < n) v0 = in[base + 0];
    if (base + 1 < n) v1 = in[base + 1];
    if (base + 2 < n) v2 = in[base + 2];
    if (base + 3 < n) v3 = in[base + 3];
    int tsum = v0 + v1 + v2 + v3;
    s[t] = tsum;
    __syncthreads();
    for (int o = 1; o < 256; o <<= 1) {
        int x = (t >= o) ? s[t - o] : 0;
        __syncthreads();
        s[t] += x;
        __syncthreads();
    }
    int excl = s[t] - tsum;
    if (t == 255) g_bsums[blockIdx.x] = s[255];
    if (base + 0 < n) out[base + 0] = excl;
    if (base + 1 < n) out[base + 1] = excl + v0;
    if (base + 2 < n) out[base + 2] = excl + v0 + v1;
    if (base + 3 < n) out[base + 3] = excl + v0 + v1 + v2;
}

__global__ void scan2_kernel(int nb) {
    __shared__ int s[512];
    int t = threadIdx.x;
    int v = (t < nb) ? g_bsums[t] : 0;
    s[t] = v;
    __syncthreads();
    for (int o = 1; o < 512; o <<= 1) {
        int x = (t >= o) ? s[t - o] : 0;
        __syncthreads();
        s[t] += x;
        __syncthreads();
    }
    if (t < nb) g_bsums[t] = s[t] - v;   // exclusive
}

__global__ void scan3_kernel(int* __restrict__ off, int* __restrict__ cur, int n) {
    int i = blockIdx.x * blockDim.x + threadIdx.x;
    if (i >= n) return;
    int o = off[i] + g_bsums[i >> 10];
    off[i] = o;
    cur[i] = o;
}

__global__ void fill_kernel(const int* __restrict__ ei, const int* __restrict__ et) {
    int e = blockIdx.x * blockDim.x + threadIdx.x;
    if (e >= E_EDGES) return;
    int key = ei[E_EDGES + e] * NUM_REL + et[e];
    int p = atomicAdd(&g_cur[key], 1);
    g_srcs[p] = ei[e];
}

// ---------------------------------------------------------------------------
// Gather-reduce aggregation (one warp per (node, rel) key) → writes mean into
// g_A[n, (1+r)*DIN : (2+r)*DIN].
// ---------------------------------------------------------------------------
template <int DIN>
__global__ void gather_agg_kernel(const float* __restrict__ feat) {
    const int K = DIN * (NUM_REL + 1);
    int w = (blockIdx.x * blockDim.x + threadIdx.x) >> 5;
    int lane = threadIdx.x & 31;
    if (w >= NKEYS) return;
    int n = w >> 3;
    int r = w & 7;
    int off = g_off[w];
    int cnt = g_deg[w];

    float4 a0 = make_float4(0.f, 0.f, 0.f, 0.f);
    float4 a1 = make_float4(0.f, 0.f, 0.f, 0.f);

    int i = 0;
    for (; i + 2 <= cnt; i += 2) {
        int s0 = g_srcs[off + i];
        int s1 = g_srcs[off + i + 1];
        const float4* p0 = (const float4*)(feat + (size_t)s0 * DIN) + lane;
        const float4* p1 = (const float4*)(feat + (size_t)s1 * DIN) + lane;
        float4 v0 = __ldg(p0);
        float4 v1 = __ldg(p1);
        float4 u0, u1;
        if (DIN == 256) { u0 = __ldg(p0 + 32); u1 = __ldg(p1 + 32); }
        a0.x += v0.x + v1.x; a0.y += v0.y + v1.y;
        a0.z += v0.z + v1.z; a0.w += v0.w + v1.w;
        if (DIN == 256) {
            a1.x += u0.x + u1.x; a1.y += u0.y + u1.y;
            a1.z += u0.z + u1.z; a1.w += u0.w + u1.w;
        }
    }
    if (i < cnt) {
        int s0 = g_srcs[off + i];
        const float4* p0 = (const float4*)(feat + (size_t)s0 * DIN) + lane;
        float4 v0 = __ldg(p0);
        a0.x += v0.x; a0.y += v0.y; a0.z += v0.z; a0.w += v0.w;
        if (DIN == 256) {
            float4 u0 = __ldg(p0 + 32);
            a1.x += u0.x; a1.y += u0.y; a1.z += u0.z; a1.w += u0.w;
        }
    }

    float sc = 1.0f / fmaxf((float)cnt, 1.0f);
    a0.x *= sc; a0.y *= sc; a0.z *= sc; a0.w *= sc;
    float4* dst = (float4*)(g_A + (size_t)n * K + (1 + r) * DIN) + lane;
    *dst = a0;
    if (DIN == 256) {
        a1.x *= sc; a1.y *= sc; a1.z *= sc; a1.w *= sc;
        *(dst + 32) = a1;
    }
}

template <int DIN>
__global__ void copy_feat_kernel(const float* __restrict__ feat) {
    const int K = DIN * (NUM_REL + 1);
    const int L = DIN / 4;
    int idx = blockIdx.x * blockDim.x + threadIdx.x;
    if (idx >= N_NODES * L) return;
    int n = idx / L;
    int j = idx % L;
    *((float4*)(g_A + (size_t)n * K) + j) = *((const float4*)(feat + (size_t)n * DIN) + j);
}

// ---------------------------------------------------------------------------
__global__ void build_B_kernel(const float* __restrict__ root,
                               const float* __restrict__ W, int Kin) {
    int total = Kin * (NUM_REL + 1) * HID;
    int idx = blockIdx.x * blockDim.x + threadIdx.x;
    if (idx >= total) return;
    int rootN = Kin * HID;
    g_B[idx] = (idx < rootN) ? root[idx] : W[idx - rootN];
}

// B' (256 x 512): cols 0..255 = mw1_top (rows 0..255), cols 256..511 = mw1_bot
__global__ void build_Bdec_kernel(const float* __restrict__ mw1) {
    int idx = blockIdx.x * blockDim.x + threadIdx.x;   // 256*512
    if (idx >= HID * 2 * HID) return;
    int k = idx >> 9;          // 0..255
    int n = idx & 511;         // 0..511
    float v = (n < HID) ? mw1[k * HID + n] : mw1[(HID + k) * HID + (n - HID)];
    g_B[idx] = v;
}

// ---------------------------------------------------------------------------
// BF16 tensor-core GEMM with 3-term error compensation (hi*hi + hi*lo + lo*hi).
// C[M,N] = A[M,K] @ B[K,N] + bias[N] (bias may be null), optional exact GELU.
// 128x128 block tile, BK=16, 8 warps, warp tile 64x32, mma.m16n8k16.bf16.
// Smem: one uint32 per element packing (lo<<16 | hi). K%16==0, N%128==0.
// ---------------------------------------------------------------------------
#define GSTRIDE 132

__device__ __forceinline__ uint32_t bf16_split_pack(float x) {
    __nv_bfloat16 h = __float2bfloat16(x);
    float hf = __bfloat162float(h);
    __nv_bfloat16 l = __float2bfloat16(x - hf);
    return ((uint32_t)__bfloat16_as_ushort(l) << 16) | (uint32_t)__bfloat16_as_ushort(h);
}

#define MMA_BF16(d, a, b)                                                     \
    asm volatile("mma.sync.aligned.m16n8k16.row.col.f32.bf16.bf16.f32 "       \
                 "{%0,%1,%2,%3}, {%4,%5,%6,%7}, {%8,%9}, {%0,%1,%2,%3};"      \
                 : "+f"(d[0]), "+f"(d[1]), "+f"(d[2]), "+f"(d[3])             \
                 : "r"(a[0]), "r"(a[1]), "r"(a[2]), "r"(a[3]),                \
                   "r"(b[0]), "r"(b[1]))

__global__ __launch_bounds__(256, 2)
void gemm_bf16x3_kernel(const float* __restrict__ A, const float* __restrict__ B,
                        float* __restrict__ C, const float* __restrict__ bias,
                        int M, int N, int K, int act) {
    __shared__ uint32_t As[16 * GSTRIDE];   // [k][m] packed (lo,hi)
    __shared__ uint32_t Bs[16 * GSTRIDE];   // [k][n] packed (lo,hi)

    const int tid  = threadIdx.x;
    const int warp = tid >> 5, lane = tid & 31;
    const int gid  = lane >> 2, tig = lane & 3;
    const int wm   = (warp & 1) * 64, wn = (warp >> 1) * 32;
    const int brow = blockIdx.y * 128, bcol = blockIdx.x * 128;

    float acc[4][4][4];
#pragma unroll
    for (int i = 0; i < 4; i++)
#pragma unroll
        for (int j = 0; j < 4; j++)
#pragma unroll
            for (int c = 0; c < 4; c++) acc[i][j][c] = 0.f;

    const int arow = tid >> 1;            // 0..127
    const int akh  = (tid & 1) * 8;       // 0 or 8
    const int bkk  = tid >> 4;            // 0..15
    const int bn0  = (tid & 15) * 8;      // 0..120

    const bool arow_ok = (brow + arow) < M;
    const float* aptr = A + (size_t)(brow + arow) * K + akh;
    const float* bptr = B + (size_t)bkk * N + bcol + bn0;

    for (int k0 = 0; k0 < K; k0 += 16) {
        // ---- stage A (transposed, packed bf16 hi/lo) ----
        float4 av0 = make_float4(0.f, 0.f, 0.f, 0.f);
        float4 av1 = make_float4(0.f, 0.f, 0.f, 0.f);
        if (arow_ok) {
            av0 = *(const float4*)(aptr + k0);
            av1 = *(const float4*)(aptr + k0 + 4);
        }
        {
            float a[8] = {av0.x, av0.y, av0.z, av0.w, av1.x, av1.y, av1.z, av1.w};
#pragma unroll
            for (int i = 0; i < 8; i++)
                As[(akh + i) * GSTRIDE + arow] = bf16_split_pack(a[i]);
        }
        // ---- stage B ----
        {
            float4 bv0 = *(const float4*)(bptr + (size_t)k0 * N);
            float4 bv1 = *(const float4*)(bptr + (size_t)k0 * N + 4);
            float b[8] = {bv0.x, bv0.y, bv0.z, bv0.w, bv1.x, bv1.y, bv1.z, bv1.w};
            uint32_t* dst = &Bs[bkk * GSTRIDE + bn0];
#pragma unroll
            for (int i = 0; i < 8; i++) dst[i] = bf16_split_pack(b[i]);
        }
        __syncthreads();

        // ---- compute: one k=16 step ----
        uint32_t bh[4][2], bl[4][2];
#pragma unroll
        for (int nt = 0; nt < 4; nt++) {
            int n = wn + nt * 8 + gid;
            uint32_t r0 = Bs[(tig * 2 + 0) * GSTRIDE + n];
            uint32_t r1 = Bs[(tig * 2 + 1) * GSTRIDE + n];
            uint32_t r2 = Bs[(tig * 2 + 8) * GSTRIDE + n];
            uint32_t r3 = Bs[(tig * 2 + 9) * GSTRIDE + n];
            bh[nt][0] = __byte_perm(r0, r1, 0x5410);
            bh[nt][1] = __byte_perm(r2, r3, 0x5410);
            bl[nt][0] = __byte_perm(r0, r1, 0x7632);
            bl[nt][1] = __byte_perm(r2, r3, 0x7632);
        }
#pragma unroll
        for (int mt = 0; mt < 4; mt++) {
            int m0 = wm + mt * 16 + gid;
            uint32_t q0 = As[(tig * 2 + 0) * GSTRIDE + m0];
            uint32_t q1 = As[(tig * 2 + 1) * GSTRIDE + m0];
            uint32_t q2 = As[(tig * 2 + 0) * GSTRIDE + m0 + 8];
            uint32_t q3 = As[(tig * 2 + 1) * GSTRIDE + m0 + 8];
            uint32_t q4 = As[(tig * 2 + 8) * GSTRIDE + m0];
            uint32_t q5 = As[(tig * 2 + 9) * GSTRIDE + m0];
            uint32_t q6 = As[(tig * 2 + 8) * GSTRIDE + m0 + 8];
            uint32_t q7 = As[(tig * 2 + 9) * GSTRIDE + m0 + 8];
            uint32_t ah[4] = {__byte_perm(q0, q1, 0x5410), __byte_perm(q2, q3, 0x5410),
                              __byte_perm(q4, q5, 0x5410), __byte_perm(q6, q7, 0x5410)};
            uint32_t al[4] = {__byte_perm(q0, q1, 0x7632), __byte_perm(q2, q3, 0x7632),
                              __byte_perm(q4, q5, 0x7632), __byte_perm(q6, q7, 0x7632)};
#pragma unroll
            for (int nt = 0; nt < 4; nt++) {
                MMA_BF16(acc[mt][nt], ah, bh[nt]);   // hi*hi
                MMA_BF16(acc[mt][nt], ah, bl[nt]);   // hi*lo
                MMA_BF16(acc[mt][nt], al, bh[nt]);   // lo*hi
            }
        }
        __syncthreads();
    }

    // ---- epilogue ----
#pragma unroll
    for (int mt = 0; mt < 4; mt++) {
        int r0 = brow + wm + mt * 16 + gid;
#pragma unroll
        for (int nt = 0; nt < 4; nt++) {
            int c = bcol + wn + nt * 8 + 2 * tig;
            float bb0 = bias ? bias[c] : 0.f;
            float bb1 = bias ? bias[c + 1] : 0.f;
            float v0 = acc[mt][nt][0] + bb0;
            float v1 = acc[mt][nt][1] + bb1;
            float v2 = acc[mt][nt][2] + bb0;
            float v3 = acc[mt][nt][3] + bb1;
            if (act == 1) {
                const float is2 = 0.70710678118654752f;
                v0 = 0.5f * v0 * (1.0f + erff(v0 * is2));
                v1 = 0.5f * v1 * (1.0f + erff(v1 * is2));
                v2 = 0.5f * v2 * (1.0f + erff(v2 * is2));
                v3 = 0.5f * v3 * (1.0f + erff(v3 * is2));
            }
            if (r0 < M)
                *(float2*)(C + (size_t)r0 * N + c) = make_float2(v0, v1);
            if (r0 + 8 < M)
                *(float2*)(C + (size_t)(r0 + 8) * N + c) = make_float2(v2, v3);
        }
    }
}

// ---------------------------------------------------------------------------
__global__ void relu_ln_kernel(const float* __restrict__ hp,
                               const float* __restrict__ g,
                               const float* __restrict__ b,
                               float* __restrict__ out,
                               const float* __restrict__ resid) {
    int row = blockIdx.x;
    int tid = threadIdx.x;   // 256 == HID
    float v = fmaxf(hp[(size_t)row * HID + tid], 0.0f);

    __shared__ float red[8];
    __shared__ float s_mu, s_rs;

    float s = v;
#pragma unroll
    for (int o = 16; o; o >>= 1) s += __shfl_xor_sync(0xFFFFFFFFu, s, o);
    if ((tid & 31) == 0) red[tid >> 5] = s;
    __syncthreads();
    if (tid == 0) {
        float t = 0.f;
#pragma unroll
        for (int i = 0; i < 8; i++) t += red[i];
        s_mu = t / (float)HID;
    }
    __syncthreads();

    float d = v - s_mu;
    float s2 = d * d;
#pragma unroll
    for (int o = 16; o; o >>= 1) s2 += __shfl_xor_sync(0xFFFFFFFFu, s2, o);
    if ((tid & 31) == 0) red[tid >> 5] = s2;
    __syncthreads();
    if (tid == 0) {
        float t = 0.f;
#pragma unroll
        for (int i = 0; i < 8; i++) t += red[i];
        s_rs = rsqrtf(t / (float)HID + 1e-5f);
    }
    __syncthreads();

    float o = d * s_rs * g[tid] + b[tid];
    if (resid) o += resid[(size_t)row * HID + tid];
    out[(size_t)row * HID + tid] = o;
}

// ---------------------------------------------------------------------------
// Fused decoder stage 1: Z1[m,c] = gelu(P[u][c] + P[v][256+c] + b1[c])
// ---------------------------------------------------------------------------
__global__ void decode_fuse_kernel(const int* __restrict__ dec,
                                   const float* __restrict__ b1) {
    int idx = blockIdx.x * blockDim.x + threadIdx.x;    // M_DEC * 64
    if (idx >= M_DEC * (HID / 4)) return;
    int m = idx >> 6;
    int j = idx & 63;          // float4 index, c = 4j
    int u = dec[m * 2 + 0];
    int v = dec[m * 2 + 1];
    float4 p = __ldg((const float4*)(g_P + (size_t)u * 512) + j);
    float4 q = __ldg((const float4*)(g_P + (size_t)v * 512 + 256) + j);
    float4 bb = *((const float4*)b1 + j);
    float4 z;
    const float is2 = 0.70710678118654752f;
    z.x = p.x + q.x + bb.x; z.x = 0.5f * z.x * (1.0f + erff(z.x * is2));
    z.y = p.y + q.y + bb.y; z.y = 0.5f * z.y * (1.0f + erff(z.y * is2));
    z.z = p.z + q.z + bb.z; z.z = 0.5f * z.z * (1.0f + erff(z.z * is2));
    z.w = p.w + q.w + bb.w; z.w = 0.5f * z.w * (1.0f + erff(z.w * is2));
    *((float4*)(g_Z1 + (size_t)m * HID) + j) = z;
}

// ---------------------------------------------------------------------------
__global__ void final_kernel(const float* __restrict__ w3,
                             const float* __restrict__ b3,
                             float* __restrict__ out) {
    long long t = (long long)blockIdx.x * blockDim.x + threadIdx.x;
    int m = (int)(t >> 5);
    int lane = (int)(t & 31);
    if (m >= M_DEC) return;
    float4 z = *(const float4*)(g_Z2 + (size_t)m * 128 + lane * 4);
    const float* w = w3 + lane * 4 * 2;
    float s0 = z.x * w[0] + z.y * w[2] + z.z * w[4] + z.w * w[6];
    float s1 = z.x * w[1] + z.y * w[3] + z.z * w[5] + z.w * w[7];
#pragma unroll
    for (int o = 16; o; o >>= 1) {
        s0 += __shfl_xor_sync(0xFFFFFFFFu, s0, o);
        s1 += __shfl_xor_sync(0xFFFFFFFFu, s1, o);
    }
    if (lane == 0) {
        out[m * 2 + 0] = s0 + b3[0];
        out[m * 2 + 1] = s1 + b3[1];
    }
}

// ---------------------------------------------------------------------------
static inline int blocks_for(long long n, int bs) { return (int)((n + bs - 1) / bs); }

extern "C" void kernel_launch(void* const* d_in, const int* in_sizes, int n_in,
                              void* d_out, int out_size) {
    const float* x     = (const float*)d_in[0];
    const int*   ei    = (const int*)  d_in[1];
    const int*   et    = (const int*)  d_in[2];
    const int*   dec   = (const int*)  d_in[3];
    const float* W1    = (const float*)d_in[4];
    const float* root1 = (const float*)d_in[5];
    const float* b1    = (const float*)d_in[6];
    const float* W2    = (const float*)d_in[7];
    const float* root2 = (const float*)d_in[8];
    const float* b2    = (const float*)d_in[9];
    const float* ln1g  = (const float*)d_in[10];
    const float* ln1b  = (const float*)d_in[11];
    const float* ln2g  = (const float*)d_in[12];
    const float* ln2b  = (const float*)d_in[13];
    const float* mw1   = (const float*)d_in[14];
    const float* mb1   = (const float*)d_in[15];
    const float* mw2   = (const float*)d_in[16];
    const float* mb2   = (const float*)d_in[17];
    const float* mw3   = (const float*)d_in[18];
    const float* mb3   = (const float*)d_in[19];
    float* out = (float*)d_out;

    float *A, *B, *hp, *h1, *h, *P, *Z1;
    int *deg, *off, *cur;
    cudaGetSymbolAddress((void**)&A,   g_A);
    cudaGetSymbolAddress((void**)&B,   g_B);
    cudaGetSymbolAddress((void**)&hp,  g_hp);
    cudaGetSymbolAddress((void**)&h1,  g_h1);
    cudaGetSymbolAddress((void**)&h,   g_h);
    cudaGetSymbolAddress((void**)&P,   g_P);
    cudaGetSymbolAddress((void**)&Z1,  g_Z1);
    cudaGetSymbolAddress((void**)&deg, g_deg);
    cudaGetSymbolAddress((void**)&off, g_off);
    cudaGetSymbolAddress((void**)&cur, g_cur);
    float *Z2;
    cudaGetSymbolAddress((void**)&Z2,  g_Z2);

    // ===================== CSR build (shared by both layers) =====================
    {
        zero_int_kernel<<<blocks_for(NKEYS / 4, 256), 256>>>(deg, NKEYS / 4);
        hist_kernel<<<blocks_for(E_EDGES, 256), 256>>>(ei, et);
        int nblk = (NKEYS + 1023) / 1024;     // 391
        scan1_kernel<<<nblk, 256>>>(deg, off, NKEYS);
        scan2_kernel<<<1, 512>>>(nblk);
        scan3_kernel<<<blocks_for(NKEYS, 256), 256>>>(off, cur, NKEYS);
        fill_kernel<<<blocks_for(E_EDGES, 256), 256>>>(ei, et);
    }

    // ===================== Layer 1 (K = 1152) =====================
    {
        copy_feat_kernel<IN_DIM><<<blocks_for(N_NODES * (IN_DIM / 4), 256), 256>>>(x);
        gather_agg_kernel<IN_DIM><<<blocks_for((long long)NKEYS * 32, 256), 256>>>(x);
        build_B_kernel<<<blocks_for(1152 * HID, 256), 256>>>(root1, W1, IN_DIM);

        dim3 grid(HID / 128, (N_NODES + 127) / 128);
        gemm_bf16x3_kernel<<<grid, 256>>>(A, B, hp, b1, N_NODES, HID, 1152, 0);

        relu_ln_kernel<<<N_NODES, HID>>>(hp, ln1g, ln1b, h1, nullptr);
    }

    // ===================== Layer 2 (K = 2304) =====================
    {
        copy_feat_kernel<HID><<<blocks_for(N_NODES * (HID / 4), 256), 256>>>(h1);
        gather_agg_kernel<HID><<<blocks_for((long long)NKEYS * 32, 256), 256>>>(h1);
        build_B_kernel<<<blocks_for(2304 * HID, 256), 256>>>(root2, W2, HID);

        dim3 grid(HID / 128, (N_NODES + 127) / 128);
        gemm_bf16x3_kernel<<<grid, 256>>>(A, B, hp, b2, N_NODES, HID, 2304, 0);

        relu_ln_kernel<<<N_NODES, HID>>>(hp, ln2g, ln2b, h, h1);
    }

    // ===================== Decoder =====================
    {
        // P = h @ [W1_top | W1_bot]  (50000 x 512), no bias/act
        build_Bdec_kernel<<<blocks_for(HID * 2 * HID, 256), 256>>>(mw1);
        dim3 gp(4, (N_NODES + 127) / 128);
        gemm_bf16x3_kernel<<<gp, 256>>>(h, B, P, nullptr, N_NODES, 2 * HID, HID, 0);

        // Z1 = gelu(P[u][:256] + P[v][256:] + mb1)
        decode_fuse_kernel<<<blocks_for((long long)M_DEC * (HID / 4), 256), 256>>>(dec, mb1);

        // Z2 = gelu(Z1 @ mw2 + mb2)
        dim3 g2((HID / 2) / 128, (M_DEC + 127) / 128);
        gemm_bf16x3_kernel<<<g2, 256>>>(Z1, mw2, Z2, mb2, M_DEC, HID / 2, HID, 1);

        final_kernel<<<blocks_for((long long)M_DEC * 32, 256), 256>>>(mw3, mb3, out);
    }
}

// round 7
// speedup vs baseline: 3.7047x; 1.1354x over previous
#include <cuda_runtime.h>
#include <cuda_bf16.h>
#include <cstdint>
#include <cstddef>

#define N_NODES 50000
#define NUM_REL 8
#define IN_DIM  128
#define HID     256
#define E_EDGES 1600000
#define M_DEC   200000
#define NKEYS   (N_NODES * NUM_REL)      // 400000

// ---------------------------------------------------------------------------
// Device scratch (static globals — no allocation allowed)
// Packed format ("ps32"): one uint32 per element = (bf16(lo) << 16) | bf16(hi),
// where hi = bf16(x), lo = bf16(x - float(hi)).
// ---------------------------------------------------------------------------
__device__ int      g_deg[NKEYS];
__device__ int      g_off[NKEYS];
__device__ int      g_cur[NKEYS];
__device__ int      g_srcs[E_EDGES];
__device__ int      g_bsums[512];
__device__ uint32_t g_A[(size_t)N_NODES * (HID + NUM_REL * HID)];   // packed, N x 2304
__device__ uint32_t g_B[(HID + NUM_REL * HID) * HID];               // packed, 2304 x 256
__device__ float    g_hp[(size_t)N_NODES * HID];
__device__ float    g_h1[(size_t)N_NODES * HID];
__device__ uint32_t g_hP[(size_t)N_NODES * HID];                    // packed final h
__device__ float    g_P [(size_t)N_NODES * 2 * HID];                // 50000 x 512
__device__ uint32_t g_Z1[(size_t)M_DEC * HID];                      // packed
__device__ float    g_Z2[(size_t)M_DEC * (HID / 2)];

// ---------------------------------------------------------------------------
__device__ __forceinline__ uint32_t bf16_split_pack(float x) {
    __nv_bfloat16 h = __float2bfloat16(x);
    float hf = __bfloat162float(h);
    __nv_bfloat16 l = __float2bfloat16(x - hf);
    return ((uint32_t)__bfloat16_as_ushort(l) << 16) | (uint32_t)__bfloat16_as_ushort(h);
}

__global__ void zero_int_kernel(int* __restrict__ p, int n4) {
    int i = blockIdx.x * blockDim.x + threadIdx.x;
    if (i < n4) ((int4*)p)[i] = make_int4(0, 0, 0, 0);
}

// ---------------------------------------------------------------------------
// CSR build over keys (dst*8 + rel)
// ---------------------------------------------------------------------------
__global__ void hist_kernel(const int* __restrict__ ei, const int* __restrict__ et) {
    int e = blockIdx.x * blockDim.x + threadIdx.x;
    if (e >= E_EDGES) return;
    int key = ei[E_EDGES + e] * NUM_REL + et[e];
    atomicAdd(&g_deg[key], 1);
}

__global__ void scan1_kernel(const int* __restrict__ in, int* __restrict__ out, int n) {
    __shared__ int s[256];
    int t = threadIdx.x;
    int base = blockIdx.x * 1024 + t * 4;
    int v0 = 0, v1 = 0, v2 = 0, v3 = 0;
    if (base + 0 < n) v0 = in[base + 0];
    if (base + 1 < n) v1 = in[base + 1];
    if (base + 2 < n) v2 = in[base + 2];
    if (base + 3 < n) v3 = in[base + 3];
    int tsum = v0 + v1 + v2 + v3;
    s[t] = tsum;
    __syncthreads();
    for (int o = 1; o < 256; o <<= 1) {
        int x = (t >= o) ? s[t - o] : 0;
        __syncthreads();
        s[t] += x;
        __syncthreads();
    }
    int excl = s[t] - tsum;
    if (t == 255) g_bsums[blockIdx.x] = s[255];
    if (base + 0 < n) out[base + 0] = excl;
    if (base + 1 < n) out[base + 1] = excl + v0;
    if (base + 2 < n) out[base + 2] = excl + v0 + v1;
    if (base + 3 < n) out[base + 3] = excl + v0 + v1 + v2;
}

__global__ void scan2_kernel(int nb) {
    __shared__ int s[512];
    int t = threadIdx.x;
    int v = (t < nb) ? g_bsums[t] : 0;
    s[t] = v;
    __syncthreads();
    for (int o = 1; o < 512; o <<= 1) {
        int x = (t >= o) ? s[t - o] : 0;
        __syncthreads();
        s[t] += x;
        __syncthreads();
    }
    if (t < nb) g_bsums[t] = s[t] - v;   // exclusive
}

__global__ void scan3_kernel(int* __restrict__ off, int* __restrict__ cur, int n) {
    int i = blockIdx.x * blockDim.x + threadIdx.x;
    if (i >= n) return;
    int o = off[i] + g_bsums[i >> 10];
    off[i] = o;
    cur[i] = o;
}

__global__ void fill_kernel(const int* __restrict__ ei, const int* __restrict__ et) {
    int e = blockIdx.x * blockDim.x + threadIdx.x;
    if (e >= E_EDGES) return;
    int key = ei[E_EDGES + e] * NUM_REL + et[e];
    int p = atomicAdd(&g_cur[key], 1);
    g_srcs[p] = ei[e];
}

// ---------------------------------------------------------------------------
// Gather-reduce aggregation (one warp per (node, rel) key) → packed mean into
// g_A[n, (1+r)*DIN : (2+r)*DIN].
// ---------------------------------------------------------------------------
template <int DIN>
__global__ void gather_agg_kernel(const float* __restrict__ feat) {
    const int K = DIN * (NUM_REL + 1);
    int w = (blockIdx.x * blockDim.x + threadIdx.x) >> 5;
    int lane = threadIdx.x & 31;
    if (w >= NKEYS) return;
    int n = w >> 3;
    int r = w & 7;
    int off = g_off[w];
    int cnt = g_deg[w];

    float4 a0 = make_float4(0.f, 0.f, 0.f, 0.f);
    float4 a1 = make_float4(0.f, 0.f, 0.f, 0.f);

    int i = 0;
    for (; i + 2 <= cnt; i += 2) {
        int s0 = g_srcs[off + i];
        int s1 = g_srcs[off + i + 1];
        const float4* p0 = (const float4*)(feat + (size_t)s0 * DIN) + lane;
        const float4* p1 = (const float4*)(feat + (size_t)s1 * DIN) + lane;
        float4 v0 = __ldg(p0);
        float4 v1 = __ldg(p1);
        float4 u0, u1;
        if (DIN == 256) { u0 = __ldg(p0 + 32); u1 = __ldg(p1 + 32); }
        a0.x += v0.x + v1.x; a0.y += v0.y + v1.y;
        a0.z += v0.z + v1.z; a0.w += v0.w + v1.w;
        if (DIN == 256) {
            a1.x += u0.x + u1.x; a1.y += u0.y + u1.y;
            a1.z += u0.z + u1.z; a1.w += u0.w + u1.w;
        }
    }
    if (i < cnt) {
        int s0 = g_srcs[off + i];
        const float4* p0 = (const float4*)(feat + (size_t)s0 * DIN) + lane;
        float4 v0 = __ldg(p0);
        a0.x += v0.x; a0.y += v0.y; a0.z += v0.z; a0.w += v0.w;
        if (DIN == 256) {
            float4 u0 = __ldg(p0 + 32);
            a1.x += u0.x; a1.y += u0.y; a1.z += u0.z; a1.w += u0.w;
        }
    }

    float sc = 1.0f / fmaxf((float)cnt, 1.0f);
    uint4 o0;
    o0.x = bf16_split_pack(a0.x * sc);
    o0.y = bf16_split_pack(a0.y * sc);
    o0.z = bf16_split_pack(a0.z * sc);
    o0.w = bf16_split_pack(a0.w * sc);
    uint4* dst = (uint4*)(g_A + (size_t)n * K + (1 + r) * DIN) + lane;
    *dst = o0;
    if (DIN == 256) {
        uint4 o1;
        o1.x = bf16_split_pack(a1.x * sc);
        o1.y = bf16_split_pack(a1.y * sc);
        o1.z = bf16_split_pack(a1.z * sc);
        o1.w = bf16_split_pack(a1.w * sc);
        *(dst + 32) = o1;
    }
}

template <int DIN>
__global__ void copy_feat_kernel(const float* __restrict__ feat) {
    const int K = DIN * (NUM_REL + 1);
    const int L = DIN / 4;
    int idx = blockIdx.x * blockDim.x + threadIdx.x;
    if (idx >= N_NODES * L) return;
    int n = idx / L;
    int j = idx % L;
    float4 v = *((const float4*)(feat + (size_t)n * DIN) + j);
    uint4 o;
    o.x = bf16_split_pack(v.x);
    o.y = bf16_split_pack(v.y);
    o.z = bf16_split_pack(v.z);
    o.w = bf16_split_pack(v.w);
    *((uint4*)(g_A + (size_t)n * K) + j) = o;
}

// ---------------------------------------------------------------------------
__global__ void build_B_kernel(const float* __restrict__ root,
                               const float* __restrict__ W, int Kin) {
    int total = Kin * (NUM_REL + 1) * HID;
    int idx = blockIdx.x * blockDim.x + threadIdx.x;
    if (idx >= total) return;
    int rootN = Kin * HID;
    float v = (idx < rootN) ? root[idx] : W[idx - rootN];
    g_B[idx] = bf16_split_pack(v);
}

// B' (256 x 512): cols 0..255 = mw1_top, cols 256..511 = mw1_bot
__global__ void build_Bdec_kernel(const float* __restrict__ mw1) {
    int idx = blockIdx.x * blockDim.x + threadIdx.x;   // 256*512
    if (idx >= HID * 2 * HID) return;
    int k = idx >> 9;
    int n = idx & 511;
    float v = (n < HID) ? mw1[k * HID + n] : mw1[(HID + k) * HID + (n - HID)];
    g_B[idx] = bf16_split_pack(v);
}

// mw2 (256 x 128) packed into g_B
__global__ void pack_w2_kernel(const float* __restrict__ mw2) {
    int idx = blockIdx.x * blockDim.x + threadIdx.x;
    if (idx >= HID * (HID / 2)) return;
    g_B[idx] = bf16_split_pack(mw2[idx]);
}

// ---------------------------------------------------------------------------
// Packed-split BF16 GEMM, 3-term compensation, cp.async 2-stage pipeline.
// A: [M,K] packed u32, B: [K,N] packed u32, C: [M,N] fp32 (+bias, opt GELU).
// 128x128 tile, BK=16, 8 warps (warp tile 64x32), mma.m16n8k16.bf16.
// ---------------------------------------------------------------------------
#define ASTRIDE 20    // u32 per A-smem row (16 used + 4 pad); 80B, 16B-aligned
#define BSTRIDE 132   // u32 per B-smem row (128 used + 4 pad); 528B, 16B-aligned

__device__ __forceinline__ void cp16(uint32_t smem, const void* g) {
    asm volatile("cp.async.cg.shared.global [%0], [%1], 16;" :: "r"(smem), "l"(g));
}

#define MMA_BF16(d, a, b)                                                     \
    asm volatile("mma.sync.aligned.m16n8k16.row.col.f32.bf16.bf16.f32 "       \
                 "{%0,%1,%2,%3}, {%4,%5,%6,%7}, {%8,%9}, {%0,%1,%2,%3};"      \
                 : "+f"(d[0]), "+f"(d[1]), "+f"(d[2]), "+f"(d[3])             \
                 : "r"(a[0]), "r"(a[1]), "r"(a[2]), "r"(a[3]),                \
                   "r"(b[0]), "r"(b[1]))

__global__ __launch_bounds__(256, 2)
void gemm_ps_kernel(const uint32_t* __restrict__ A, const uint32_t* __restrict__ B,
                    float* __restrict__ C, const float* __restrict__ bias,
                    int M, int N, int K, int act) {
    __shared__ uint32_t As[2][128 * ASTRIDE];
    __shared__ uint32_t Bs[2][16 * BSTRIDE];

    const int tid  = threadIdx.x;
    const int warp = tid >> 5, lane = tid & 31;
    const int gid  = lane >> 2, tig = lane & 3;
    const int wm   = (warp & 1) * 64, wn = (warp >> 1) * 32;
    const int brow = blockIdx.y * 128, bcol = blockIdx.x * 128;

    float acc[4][4][4];
#pragma unroll
    for (int i = 0; i < 4; i++)
#pragma unroll
        for (int j = 0; j < 4; j++)
#pragma unroll
            for (int c = 0; c < 4; c++) acc[i][j][c] = 0.f;

    // staging map: A — thread covers row (tid>>1), u32 cols [(tid&1)*8, +8)
    //              B — thread covers k-row (tid>>4), u32 cols [(tid&15)*8, +8)
    const int ar = tid >> 1;
    const int ac = (tid & 1) * 8;
    const int br = tid >> 4;
    const int bc = (tid & 15) * 8;

    const int arow_g = min(brow + ar, M - 1);       // clamp; extra rows unused
    const uint32_t* ag = A + (size_t)arow_g * K + ac;
    const uint32_t* bg = B + (size_t)br * N + bcol + bc;

    const uint32_t a_sm0 = (uint32_t)__cvta_generic_to_shared(&As[0][ar * ASTRIDE + ac]);
    const uint32_t a_sm1 = (uint32_t)__cvta_generic_to_shared(&As[1][ar * ASTRIDE + ac]);
    const uint32_t b_sm0 = (uint32_t)__cvta_generic_to_shared(&Bs[0][br * BSTRIDE + bc]);
    const uint32_t b_sm1 = (uint32_t)__cvta_generic_to_shared(&Bs[1][br * BSTRIDE + bc]);

    const int ntiles = K >> 4;

    // prologue: load tile 0 into stage 0
    cp16(a_sm0,      ag);
    cp16(a_sm0 + 16, ag + 4);
    cp16(b_sm0,      bg);
    cp16(b_sm0 + 16, bg + 4);
    asm volatile("cp.async.commit_group;");

    for (int t = 0; t < ntiles; t++) {
        if (t + 1 < ntiles) {
            int k0 = (t + 1) << 4;
            uint32_t asm_ = ((t + 1) & 1) ? a_sm1 : a_sm0;
            uint32_t bsm_ = ((t + 1) & 1) ? b_sm1 : b_sm0;
            cp16(asm_,      ag + k0);
            cp16(asm_ + 16, ag + k0 + 4);
            cp16(bsm_,      bg + (size_t)k0 * N);
            cp16(bsm_ + 16, bg + (size_t)k0 * N + 4);
            asm volatile("cp.async.commit_group;");
            asm volatile("cp.async.wait_group 1;");
        } else {
            asm volatile("cp.async.wait_group 0;");
        }
        __syncthreads();

        const uint32_t* as = As[t & 1];
        const uint32_t* bs = Bs[t & 1];

        uint32_t bh[4][2], bl[4][2];
#pragma unroll
        for (int nt = 0; nt < 4; nt++) {
            int n = wn + nt * 8 + gid;
            uint32_t r0 = bs[(tig * 2 + 0) * BSTRIDE + n];
            uint32_t r1 = bs[(tig * 2 + 1) * BSTRIDE + n];
            uint32_t r2 = bs[(tig * 2 + 8) * BSTRIDE + n];
            uint32_t r3 = bs[(tig * 2 + 9) * BSTRIDE + n];
            bh[nt][0] = __byte_perm(r0, r1, 0x5410);
            bh[nt][1] = __byte_perm(r2, r3, 0x5410);
            bl[nt][0] = __byte_perm(r0, r1, 0x7632);
            bl[nt][1] = __byte_perm(r2, r3, 0x7632);
        }
#pragma unroll
        for (int mt = 0; mt < 4; mt++) {
            int m0 = wm + mt * 16 + gid;
            uint2 p0 = *(const uint2*)&as[m0 * ASTRIDE + tig * 2];
            uint2 p1 = *(const uint2*)&as[(m0 + 8) * ASTRIDE + tig * 2];
            uint2 p2 = *(const uint2*)&as[m0 * ASTRIDE + tig * 2 + 8];
            uint2 p3 = *(const uint2*)&as[(m0 + 8) * ASTRIDE + tig * 2 + 8];
            uint32_t ah[4] = {__byte_perm(p0.x, p0.y, 0x5410), __byte_perm(p1.x, p1.y, 0x5410),
                              __byte_perm(p2.x, p2.y, 0x5410), __byte_perm(p3.x, p3.y, 0x5410)};
            uint32_t al[4] = {__byte_perm(p0.x, p0.y, 0x7632), __byte_perm(p1.x, p1.y, 0x7632),
                              __byte_perm(p2.x, p2.y, 0x7632), __byte_perm(p3.x, p3.y, 0x7632)};
#pragma unroll
            for (int nt = 0; nt < 4; nt++) {
                MMA_BF16(acc[mt][nt], ah, bh[nt]);   // hi*hi
                MMA_BF16(acc[mt][nt], ah, bl[nt]);   // hi*lo
                MMA_BF16(acc[mt][nt], al, bh[nt]);   // lo*hi
            }
        }
        __syncthreads();
    }

    // ---- epilogue ----
#pragma unroll
    for (int mt = 0; mt < 4; mt++) {
        int r0 = brow + wm + mt * 16 + gid;
#pragma unroll
        for (int nt = 0; nt < 4; nt++) {
            int c = bcol + wn + nt * 8 + 2 * tig;
            float bb0 = bias ? bias[c] : 0.f;
            float bb1 = bias ? bias[c + 1] : 0.f;
            float v0 = acc[mt][nt][0] + bb0;
            float v1 = acc[mt][nt][1] + bb1;
            float v2 = acc[mt][nt][2] + bb0;
            float v3 = acc[mt][nt][3] + bb1;
            if (act == 1) {
                const float is2 = 0.70710678118654752f;
                v0 = 0.5f * v0 * (1.0f + erff(v0 * is2));
                v1 = 0.5f * v1 * (1.0f + erff(v1 * is2));
                v2 = 0.5f * v2 * (1.0f + erff(v2 * is2));
                v3 = 0.5f * v3 * (1.0f + erff(v3 * is2));
            }
            if (r0 < M)
                *(float2*)(C + (size_t)r0 * N + c) = make_float2(v0, v1);
            if (r0 + 8 < M)
                *(float2*)(C + (size_t)(r0 + 8) * N + c) = make_float2(v2, v3);
        }
    }
}

// ---------------------------------------------------------------------------
// Row-wise ReLU + LayerNorm; fp32 output (layer 1)
// ---------------------------------------------------------------------------
__global__ void relu_ln_kernel(const float* __restrict__ hp,
                               const float* __restrict__ g,
                               const float* __restrict__ b,
                               float* __restrict__ out) {
    int row = blockIdx.x;
    int tid = threadIdx.x;   // 256 == HID
    float v = fmaxf(hp[(size_t)row * HID + tid], 0.0f);

    __shared__ float red[8];
    __shared__ float s_mu, s_rs;

    float s = v;
#pragma unroll
    for (int o = 16; o; o >>= 1) s += __shfl_xor_sync(0xFFFFFFFFu, s, o);
    if ((tid & 31) == 0) red[tid >> 5] = s;
    __syncthreads();
    if (tid == 0) {
        float t = 0.f;
#pragma unroll
        for (int i = 0; i < 8; i++) t += red[i];
        s_mu = t / (float)HID;
    }
    __syncthreads();

    float d = v - s_mu;
    float s2 = d * d;
#pragma unroll
    for (int o = 16; o; o >>= 1) s2 += __shfl_xor_sync(0xFFFFFFFFu, s2, o);
    if ((tid & 31) == 0) red[tid >> 5] = s2;
    __syncthreads();
    if (tid == 0) {
        float t = 0.f;
#pragma unroll
        for (int i = 0; i < 8; i++) t += red[i];
        s_rs = rsqrtf(t / (float)HID + 1e-5f);
    }
    __syncthreads();

    out[(size_t)row * HID + tid] = d * s_rs * g[tid] + b[tid];
}

// Layer 2 variant: out = packed(resid + LN(relu(hp)))
__global__ void relu_ln_pack_kernel(const float* __restrict__ hp,
                                    const float* __restrict__ g,
                                    const float* __restrict__ b,
                                    uint32_t* __restrict__ outp,
                                    const float* __restrict__ resid) {
    int row = blockIdx.x;
    int tid = threadIdx.x;
    float v = fmaxf(hp[(size_t)row * HID + tid], 0.0f);

    __shared__ float red[8];
    __shared__ float s_mu, s_rs;

    float s = v;
#pragma unroll
    for (int o = 16; o; o >>= 1) s += __shfl_xor_sync(0xFFFFFFFFu, s, o);
    if ((tid & 31) == 0) red[tid >> 5] = s;
    __syncthreads();
    if (tid == 0) {
        float t = 0.f;
#pragma unroll
        for (int i = 0; i < 8; i++) t += red[i];
        s_mu = t / (float)HID;
    }
    __syncthreads();

    float d = v - s_mu;
    float s2 = d * d;
#pragma unroll
    for (int o = 16; o; o >>= 1) s2 += __shfl_xor_sync(0xFFFFFFFFu, s2, o);
    if ((tid & 31) == 0) red[tid >> 5] = s2;
    __syncthreads();
    if (tid == 0) {
        float t = 0.f;
#pragma unroll
        for (int i = 0; i < 8; i++) t += red[i];
        s_rs = rsqrtf(t / (float)HID + 1e-5f);
    }
    __syncthreads();

    float o = d * s_rs * g[tid] + b[tid] + resid[(size_t)row * HID + tid];
    outp[(size_t)row * HID + tid] = bf16_split_pack(o);
}

// ---------------------------------------------------------------------------
// Fused decoder stage 1: Z1[m,c] = packed(gelu(P[u][c] + P[v][256+c] + b1[c]))
// ---------------------------------------------------------------------------
__global__ void decode_fuse_kernel(const int* __restrict__ dec,
                                   const float* __restrict__ b1) {
    int idx = blockIdx.x * blockDim.x + threadIdx.x;    // M_DEC * 64
    if (idx >= M_DEC * (HID / 4)) return;
    int m = idx >> 6;
    int j = idx & 63;
    int u = dec[m * 2 + 0];
    int v = dec[m * 2 + 1];
    float4 p = __ldg((const float4*)(g_P + (size_t)u * 512) + j);
    float4 q = __ldg((const float4*)(g_P + (size_t)v * 512 + 256) + j);
    float4 bb = *((const float4*)b1 + j);
    const float is2 = 0.70710678118654752f;
    float zx = p.x + q.x + bb.x; zx = 0.5f * zx * (1.0f + erff(zx * is2));
    float zy = p.y + q.y + bb.y; zy = 0.5f * zy * (1.0f + erff(zy * is2));
    float zz = p.z + q.z + bb.z; zz = 0.5f * zz * (1.0f + erff(zz * is2));
    float zw = p.w + q.w + bb.w; zw = 0.5f * zw * (1.0f + erff(zw * is2));
    uint4 o;
    o.x = bf16_split_pack(zx);
    o.y = bf16_split_pack(zy);
    o.z = bf16_split_pack(zz);
    o.w = bf16_split_pack(zw);
    *((uint4*)(g_Z1 + (size_t)m * HID) + j) = o;
}

// ---------------------------------------------------------------------------
__global__ void final_kernel(const float* __restrict__ w3,
                             const float* __restrict__ b3,
                             float* __restrict__ out) {
    long long t = (long long)blockIdx.x * blockDim.x + threadIdx.x;
    int m = (int)(t >> 5);
    int lane = (int)(t & 31);
    if (m >= M_DEC) return;
    float4 z = *(const float4*)(g_Z2 + (size_t)m * 128 + lane * 4);
    const float* w = w3 + lane * 4 * 2;
    float s0 = z.x * w[0] + z.y * w[2] + z.z * w[4] + z.w * w[6];
    float s1 = z.x * w[1] + z.y * w[3] + z.z * w[5] + z.w * w[7];
#pragma unroll
    for (int o = 16; o; o >>= 1) {
        s0 += __shfl_xor_sync(0xFFFFFFFFu, s0, o);
        s1 += __shfl_xor_sync(0xFFFFFFFFu, s1, o);
    }
    if (lane == 0) {
        out[m * 2 + 0] = s0 + b3[0];
        out[m * 2 + 1] = s1 + b3[1];
    }
}

// ---------------------------------------------------------------------------
static inline int blocks_for(long long n, int bs) { return (int)((n + bs - 1) / bs); }

extern "C" void kernel_launch(void* const* d_in, const int* in_sizes, int n_in,
                              void* d_out, int out_size) {
    const float* x     = (const float*)d_in[0];
    const int*   ei    = (const int*)  d_in[1];
    const int*   et    = (const int*)  d_in[2];
    const int*   dec   = (const int*)  d_in[3];
    const float* W1    = (const float*)d_in[4];
    const float* root1 = (const float*)d_in[5];
    const float* b1    = (const float*)d_in[6];
    const float* W2    = (const float*)d_in[7];
    const float* root2 = (const float*)d_in[8];
    const float* b2    = (const float*)d_in[9];
    const float* ln1g  = (const float*)d_in[10];
    const float* ln1b  = (const float*)d_in[11];
    const float* ln2g  = (const float*)d_in[12];
    const float* ln2b  = (const float*)d_in[13];
    const float* mw1   = (const float*)d_in[14];
    const float* mb1   = (const float*)d_in[15];
    const float* mw2   = (const float*)d_in[16];
    const float* mb2   = (const float*)d_in[17];
    const float* mw3   = (const float*)d_in[18];
    const float* mb3   = (const float*)d_in[19];
    float* out = (float*)d_out;

    uint32_t *A, *B, *hP, *Z1;
    float *hp, *h1, *P, *Z2;
    int *deg, *off, *cur;
    cudaGetSymbolAddress((void**)&A,   g_A);
    cudaGetSymbolAddress((void**)&B,   g_B);
    cudaGetSymbolAddress((void**)&hp,  g_hp);
    cudaGetSymbolAddress((void**)&h1,  g_h1);
    cudaGetSymbolAddress((void**)&hP,  g_hP);
    cudaGetSymbolAddress((void**)&P,   g_P);
    cudaGetSymbolAddress((void**)&Z1,  g_Z1);
    cudaGetSymbolAddress((void**)&Z2,  g_Z2);
    cudaGetSymbolAddress((void**)&deg, g_deg);
    cudaGetSymbolAddress((void**)&off, g_off);
    cudaGetSymbolAddress((void**)&cur, g_cur);

    // ===================== CSR build (shared by both layers) =====================
    {
        zero_int_kernel<<<blocks_for(NKEYS / 4, 256), 256>>>(deg, NKEYS / 4);
        hist_kernel<<<blocks_for(E_EDGES, 256), 256>>>(ei, et);
        int nblk = (NKEYS + 1023) / 1024;     // 391
        scan1_kernel<<<nblk, 256>>>(deg, off, NKEYS);
        scan2_kernel<<<1, 512>>>(nblk);
        scan3_kernel<<<blocks_for(NKEYS, 256), 256>>>(off, cur, NKEYS);
        fill_kernel<<<blocks_for(E_EDGES, 256), 256>>>(ei, et);
    }

    // ===================== Layer 1 (K = 1152) =====================
    {
        copy_feat_kernel<IN_DIM><<<blocks_for(N_NODES * (IN_DIM / 4), 256), 256>>>(x);
        gather_agg_kernel<IN_DIM><<<blocks_for((long long)NKEYS * 32, 256), 256>>>(x);
        build_B_kernel<<<blocks_for(1152 * HID, 256), 256>>>(root1, W1, IN_DIM);

        dim3 grid(HID / 128, (N_NODES + 127) / 128);
        gemm_ps_kernel<<<grid, 256>>>(A, B, hp, b1, N_NODES, HID, 1152, 0);

        relu_ln_kernel<<<N_NODES, HID>>>(hp, ln1g, ln1b, h1);
    }

    // ===================== Layer 2 (K = 2304) =====================
    {
        copy_feat_kernel<HID><<<blocks_for(N_NODES * (HID / 4), 256), 256>>>(h1);
        gather_agg_kernel<HID><<<blocks_for((long long)NKEYS * 32, 256), 256>>>(h1);
        build_B_kernel<<<blocks_for(2304 * HID, 256), 256>>>(root2, W2, HID);

        dim3 grid(HID / 128, (N_NODES + 127) / 128);
        gemm_ps_kernel<<<grid, 256>>>(A, B, hp, b2, N_NODES, HID, 2304, 0);

        relu_ln_pack_kernel<<<N_NODES, HID>>>(hp, ln2g, ln2b, hP, h1);
    }

    // ===================== Decoder =====================
    {
        // P = h @ [W1_top | W1_bot]  (50000 x 512)
        build_Bdec_kernel<<<blocks_for(HID * 2 * HID, 256), 256>>>(mw1);
        dim3 gp(4, (N_NODES + 127) / 128);
        gemm_ps_kernel<<<gp, 256>>>(hP, B, P, nullptr, N_NODES, 2 * HID, HID, 0);

        // Z1 = packed(gelu(P[u][:256] + P[v][256:] + mb1))
        decode_fuse_kernel<<<blocks_for((long long)M_DEC * (HID / 4), 256), 256>>>(dec, mb1);

        // Z2 = gelu(Z1 @ mw2 + mb2)
        pack_w2_kernel<<<blocks_for(HID * (HID / 2), 256), 256>>>(mw2);
        dim3 g2((HID / 2) / 128, (M_DEC + 127) / 128);
        gemm_ps_kernel<<<g2, 256>>>(Z1, B, Z2, mb2, M_DEC, HID / 2, HID, 1);

        final_kernel<<<blocks_for((long long)M_DEC * 32, 256), 256>>>(mw3, mb3, out);
    }
}